// round 5
// baseline (speedup 1.0000x reference)
#include <cuda_runtime.h>

#define NB 8
#define NS 4
#define NHY 50
#define NV 200
#define NE 400
#define NL 2
#define FD 79
#define HD 128
#define WN1R 207
#define NNODE (NB*NS*NHY)

#define EDUP 260   // floats per edge row in duplicated activation buffers (256 + 4 pad)

// ------------- device scratch (no allocation) -------------
__device__ float g_cA [NNODE*HD];
__device__ float g_cBh[NNODE*HD];
__device__ float g_cBv[NB*NV*HD];
__device__ float g_feat[NNODE*FD];
__device__ float g_x   [NNODE*3];
__device__ float g_aggm[NNODE*HD];
__device__ float g_aggx[NNODE*3];
__device__ int   g_start[NB*(NHY+1)];
__device__ int   g_col[NB*NE];
__device__ float g_em [NB*NE];

__device__ __forceinline__ float silu_f(float x) {
    return __fdividef(x, 1.0f + __expf(-x));
}

__device__ __forceinline__ void ffma2(unsigned long long &d,
                                      unsigned long long a, unsigned long long b) {
    asm volatile("fma.rn.f32x2 %0, %1, %2, %0;" : "+l"(d) : "l"(a), "l"(b));
}

union F2U { unsigned long long u; float2 f; };

// ------------- CSR of h-h edges, deterministic -------------
__global__ void csr_k(const int* __restrict__ e, const float* __restrict__ em) {
    __shared__ int cnt[NHY+1];
    int b = blockIdx.x, t = threadIdx.x;
    if (t <= NHY) cnt[t] = 0;
    __syncthreads();
    if (t < NHY) {
        int c = 0;
        for (int i = 0; i < NE; i++) if (e[(b*NE+i)*2] == t) c++;
        cnt[t+1] = c;
    }
    __syncthreads();
    if (t == 0) for (int i = 0; i < NHY; i++) cnt[i+1] += cnt[i];
    __syncthreads();
    if (t <= NHY) g_start[b*(NHY+1)+t] = cnt[t];
    if (t < NHY) {
        int p = cnt[t];
        for (int i = 0; i < NE; i++) if (e[(b*NE+i)*2] == t) {
            g_col[b*NE+p] = e[(b*NE+i)*2+1];
            g_em [b*NE+p] = em[b*NE+i];
            p++;
        }
    }
}

// ------------- init: abs positions + one-hot h features -------------
__global__ void init_k(const float* __restrict__ x_h, const float* __restrict__ x_hv,
                       const int* __restrict__ bound, const int* __restrict__ labh,
                       const int* __restrict__ posh, const int* __restrict__ pept) {
    int idx = blockIdx.x*blockDim.x + threadIdx.x;
    if (idx >= NNODE) return;
    int r = idx % NHY;
    int b = idx / (NHY*NS);
    int ba = bound[b*NHY+r];
    for (int c = 0; c < 3; ++c)
        g_x[idx*3+c] = x_h[idx*3+c] + x_hv[(b*NV+ba)*3+c];
    int lab = labh[b*NHY+r], pos = posh[b*NHY+r];
    int aa = pept[b*15 + pos - 1];
    float* f = g_feat + idx*FD;
    for (int i = 0; i < FD; ++i) f[i] = 0.f;
    f[lab] = 1.f; f[44+aa] = 1.f; f[64+pos-1] = 1.f;
}

// ------------- per layer: heavy cB via one-hot gathers -------------
__global__ void heavycb_k(int l, const float* __restrict__ W1,
                          const int* __restrict__ labv, const int* __restrict__ posv,
                          const int* __restrict__ pept) {
    int idx = blockIdx.x*blockDim.x + threadIdx.x;
    if (idx >= NB*NV*HD) return;
    int k = idx % HD;
    int j = (idx / HD) % NV;
    int b = idx / (HD*NV);
    int lab = labv[b*NV+j];
    int pos = posv[b*NV+j];
    int aa  = pept[b*15 + pos - 1];
    const float* W = W1 + l*161*HD;
    g_cBv[idx] = W[(FD+lab)*HD+k] + W[(FD+44+aa)*HD+k] + W[(FD+64+pos-1)*HD+k];
}

// ------------- per layer: h-node cA (b1+t folded) and cB -------------
__global__ void hcab_k(int l, const float* __restrict__ W1,
                       const float* __restrict__ b1, const float* __restrict__ t) {
    __shared__ float fs[FD];
    int nidx = blockIdx.x;
    int b = nidx / (NHY*NS);
    int tid = threadIdx.x;
    if (tid < FD) fs[tid] = g_feat[nidx*FD+tid];
    __syncthreads();
    const float* W = W1 + l*161*HD;
    float a  = b1[l*HD+tid] + t[b]*W[160*HD+tid];
    float bb = 0.f;
    #pragma unroll 4
    for (int f = 0; f < FD; ++f) {
        float fv = fs[f];
        a  = fmaf(fv, W[f*HD+tid], a);
        bb = fmaf(fv, W[(FD+f)*HD+tid], bb);
    }
    g_cA [nidx*HD+tid] = a;
    g_cBh[nidx*HD+tid] = bb;
}

// ------------- packed GEMM: 4 edges x 4 cols per thread, K=128 -------------
// Adup: duplicated activations, EDUP-float stride per edge, value k at [2k],[2k+1]
// Ws:   plain 128x128 row-major (k-major). acc: 8 packed pairs = 4 edges x 2 col-pairs.
__device__ __forceinline__ void gemm_pk(const float* __restrict__ Adup, int eg,
                                        const float* __restrict__ Ws, int c,
                                        unsigned long long acc[8]) {
    const float* a0p = Adup + (eg     )*EDUP;
    const float* a1p = Adup + (eg +  8)*EDUP;
    const float* a2p = Adup + (eg + 16)*EDUP;
    const float* a3p = Adup + (eg + 24)*EDUP;
    #pragma unroll 8
    for (int j = 0; j < HD; j += 2) {
        ulonglong2 a0 = *(const ulonglong2*)(a0p + 2*j);
        ulonglong2 a1 = *(const ulonglong2*)(a1p + 2*j);
        ulonglong2 a2 = *(const ulonglong2*)(a2p + 2*j);
        ulonglong2 a3 = *(const ulonglong2*)(a3p + 2*j);
        ulonglong2 w0 = *(const ulonglong2*)(Ws + (j  )*HD + c);
        ulonglong2 w1 = *(const ulonglong2*)(Ws + (j+1)*HD + c);
        ffma2(acc[0], a0.x, w0.x); ffma2(acc[1], a0.x, w0.y);
        ffma2(acc[2], a1.x, w0.x); ffma2(acc[3], a1.x, w0.y);
        ffma2(acc[4], a2.x, w0.x); ffma2(acc[5], a2.x, w0.y);
        ffma2(acc[6], a3.x, w0.x); ffma2(acc[7], a3.x, w0.y);
        ffma2(acc[0], a0.y, w1.x); ffma2(acc[1], a0.y, w1.y);
        ffma2(acc[2], a1.y, w1.x); ffma2(acc[3], a1.y, w1.y);
        ffma2(acc[4], a2.y, w1.x); ffma2(acc[5], a2.y, w1.y);
        ffma2(acc[6], a3.y, w1.x); ffma2(acc[7], a3.y, w1.y);
    }
}

// smem float layout
#define OFF_W2    0
#define OFF_WC1   16384
#define OFF_M1    32768
#define OFF_M2    (OFF_M1 + 32*EDUP)
#define OFF_B2    (OFF_M2 + 32*EDUP)
#define OFF_BC1   (OFF_B2 + HD)
#define OFF_WC2   (OFF_BC1 + HD)
#define OFF_W1D   (OFF_WC2 + HD)
#define OFF_W1B   (OFF_W1D + HD)
#define OFF_CA    (OFF_W1B + HD)
#define OFF_AGGM  (OFF_CA + HD)
#define OFF_CWP   (OFF_AGGM + HD)
#define OFF_DIFF  (OFF_CWP + 32*32)
#define OFF_DIST  (OFF_DIFF + 96)
#define OFF_BOND  (OFF_DIST + 32)
#define OFF_EMS   (OFF_BOND + 32)
#define OFF_CWS   (OFF_EMS + 32)
#define OFF_XR    (OFF_CWS + 32)
#define OFF_AGGX  (OFF_XR + 4)
#define OFF_COLS  (OFF_AGGX + 4)
#define EDGE_SMEM_FLOATS (OFF_COLS + 32)
#define EDGE_SMEM_BYTES (EDGE_SMEM_FLOATS*4)

// ------------- edge kernel: 1 block per (b,s,row) -------------
__global__ void __launch_bounds__(256, 1)
edge_k(int l,
       const float* __restrict__ W1,  const float* __restrict__ W2g,
       const float* __restrict__ b2g, const float* __restrict__ Wc1g,
       const float* __restrict__ bc1g,const float* __restrict__ Wc2g,
       const float* __restrict__ x_hv,const float* __restrict__ bondm,
       const float* __restrict__ emhv) {
    extern __shared__ float es[];
    float* W2s   = es + OFF_W2;
    float* Wc1s  = es + OFF_WC1;
    float* m1d   = es + OFF_M1;
    float* m2d   = es + OFF_M2;
    float* b2s   = es + OFF_B2;
    float* bc1s  = es + OFF_BC1;
    float* wc2s  = es + OFF_WC2;
    float* w1d   = es + OFF_W1D;
    float* w1b   = es + OFF_W1B;
    float* cAs   = es + OFF_CA;
    float* aggm  = es + OFF_AGGM;
    float* cwp   = es + OFF_CWP;
    float* diffs = es + OFF_DIFF;
    float* dists = es + OFF_DIST;
    float* bonds = es + OFF_BOND;
    float* ems   = es + OFF_EMS;
    float* cws   = es + OFF_CWS;
    float* xrs   = es + OFF_XR;
    float* aggx  = es + OFF_AGGX;
    int*   colss = (int*)(es + OFF_COLS);

    int tid = threadIdx.x;
    int blk = blockIdx.x;
    int r = blk % NHY;
    int s = (blk / NHY) % NS;
    int b = blk / (NHY*NS);
    int nidx = (b*NS+s)*NHY + r;

    const float* W2p  = W2g  + l*HD*HD;
    const float* Wc1p = Wc1g + l*HD*HD;
    for (int i = tid; i < HD*HD/4; i += 256) {
        ((float4*)W2s)[i]  = ((const float4*)W2p)[i];
        ((float4*)Wc1s)[i] = ((const float4*)Wc1p)[i];
    }
    if (tid < HD) {
        b2s [tid] = b2g [l*HD+tid];
        bc1s[tid] = bc1g[l*HD+tid];
        wc2s[tid] = Wc2g[l*HD+tid];
        w1d [tid] = W1[(l*161+158)*HD+tid];
        w1b [tid] = W1[(l*161+159)*HD+tid];
        cAs [tid] = g_cA[nidx*HD+tid];
        aggm[tid] = 0.f;
    }
    if (tid < 3) { xrs[tid] = g_x[nidx*3+tid]; aggx[tid] = 0.f; }
    int hh0   = g_start[b*(NHY+1)+r];
    int hhcnt = g_start[b*(NHY+1)+r+1] - hh0;
    int ne = NV + hhcnt;
    int ntile = (ne + 31) >> 5;
    __syncthreads();

    int eg = tid & 7, cg = tid >> 3, c = cg*4;

    for (int tile = 0; tile < ntile; ++tile) {
        // --- stage 0: per-edge scalars ---
        if (tid < 32) {
            int e = tile*32 + tid;
            int col = NHY; float bond = 0.f, em = 0.f;
            float d0 = 0.f, d1 = 0.f, d2 = 0.f;
            if (e < NV) {
                col  = NHY + e;
                bond = bondm[(b*NHY+r)*NV + e];
                em   = emhv [(b*NHY+r)*NV + e];
            } else if (e < ne) {
                int ii = hh0 + (e - NV);
                col = g_col[b*NE+ii];
                em  = g_em [b*NE+ii];
            }
            if (e < ne) {
                const float* xc = (col >= NHY) ? (x_hv + (b*NV + (col-NHY))*3)
                                               : (g_x + ((b*NS+s)*NHY+col)*3);
                d0 = xrs[0]-xc[0]; d1 = xrs[1]-xc[1]; d2 = xrs[2]-xc[2];
            }
            diffs[tid*3+0]=d0; diffs[tid*3+1]=d1; diffs[tid*3+2]=d2;
            dists[tid] = sqrtf(d0*d0 + d1*d1 + d2*d2);
            bonds[tid] = bond; ems[tid] = em; colss[tid] = col;
        }
        __syncthreads();
        // --- stage 1: m1 = silu(cA + cB[col] + d*wd + bond*wb), stored DUPLICATED ---
        #pragma unroll
        for (int rep = 0; rep < 4; ++rep) {
            int q = rep*256 + tid;
            int e = q >> 5;
            int k4 = (q & 31) << 2;
            int col = colss[e];
            const float* cb = (col >= NHY) ? (g_cBv + (b*NV + (col-NHY))*HD)
                                           : (g_cBh + (((b*NS+s)*NHY)+col)*HD);
            float4 cv = *(const float4*)(cb + k4);
            float dd = dists[e], bo = bonds[e];
            float o0 = silu_f(cAs[k4+0] + cv.x + dd*w1d[k4+0] + bo*w1b[k4+0]);
            float o1 = silu_f(cAs[k4+1] + cv.y + dd*w1d[k4+1] + bo*w1b[k4+1]);
            float o2 = silu_f(cAs[k4+2] + cv.z + dd*w1d[k4+2] + bo*w1b[k4+2]);
            float o3 = silu_f(cAs[k4+3] + cv.w + dd*w1d[k4+3] + bo*w1b[k4+3]);
            float* dst = m1d + e*EDUP + 2*k4;
            *(float4*)(dst)     = make_float4(o0, o0, o1, o1);
            *(float4*)(dst + 4) = make_float4(o2, o2, o3, o3);
        }
        __syncthreads();
        // --- stage 2: m2 = silu(m1@W2 + b2) * emask  (packed f32x2 GEMM) ---
        {
            unsigned long long acc[8];
            ulonglong2 bv = *(const ulonglong2*)(b2s + c);
            acc[0]=bv.x; acc[1]=bv.y; acc[2]=bv.x; acc[3]=bv.y;
            acc[4]=bv.x; acc[5]=bv.y; acc[6]=bv.x; acc[7]=bv.y;
            gemm_pk(m1d, eg, W2s, c, acc);
            #pragma unroll
            for (int u = 0; u < 4; ++u) {
                int e = eg + u*8;
                float em = ems[e];
                F2U p0, p1; p0.u = acc[2*u]; p1.u = acc[2*u+1];
                float f0 = silu_f(p0.f.x)*em, f1 = silu_f(p0.f.y)*em;
                float f2 = silu_f(p1.f.x)*em, f3 = silu_f(p1.f.y)*em;
                float* dst = m2d + e*EDUP + 2*c;
                *(float4*)(dst)     = make_float4(f0, f0, f1, f1);
                *(float4*)(dst + 4) = make_float4(f2, f2, f3, f3);
            }
        }
        __syncthreads();
        // --- stage 3: cw = silu(m2@Wc1 + bc1) . Wc2  (packed f32x2 GEMM) ---
        {
            unsigned long long acc[8];
            ulonglong2 bv = *(const ulonglong2*)(bc1s + c);
            acc[0]=bv.x; acc[1]=bv.y; acc[2]=bv.x; acc[3]=bv.y;
            acc[4]=bv.x; acc[5]=bv.y; acc[6]=bv.x; acc[7]=bv.y;
            gemm_pk(m2d, eg, Wc1s, c, acc);
            float wa = wc2s[c], wb2 = wc2s[c+1], wcc = wc2s[c+2], wd = wc2s[c+3];
            #pragma unroll
            for (int u = 0; u < 4; ++u) {
                int e = eg + u*8;
                F2U p0, p1; p0.u = acc[2*u]; p1.u = acc[2*u+1];
                float cw = silu_f(p0.f.x)*wa + silu_f(p0.f.y)*wb2
                         + silu_f(p1.f.x)*wcc + silu_f(p1.f.y)*wd;
                cwp[e*32 + cg] = cw;
            }
        }
        __syncthreads();
        // --- stage 4a: aggregate m2, reduce cw partials ---
        if (tid < HD) {
            float a = aggm[tid];
            #pragma unroll
            for (int e = 0; e < 32; ++e) a += m2d[e*EDUP + 2*tid];
            aggm[tid] = a;
        } else if (tid < HD + 32) {
            int e = tid - HD;
            float sum = 0.f;
            #pragma unroll
            for (int i = 0; i < 32; ++i) sum += cwp[e*32+i];
            cws[e] = sum;
        }
        __syncthreads();
        // --- stage 4b: aggregate diff*cw ---
        if (tid < 3) {
            float a = aggx[tid];
            #pragma unroll
            for (int e = 0; e < 32; ++e) a += diffs[e*3+tid]*cws[e];
            aggx[tid] = a;
        }
        __syncthreads();
    }
    if (tid < HD) g_aggm[nidx*HD+tid] = aggm[tid];
    if (tid < 3)  g_aggx[nidx*3+tid]  = aggx[tid];
}

// ------------- node update -------------
__global__ void node_k(int l, const float* __restrict__ Wn1, const float* __restrict__ bn1,
                       const float* __restrict__ Wn2, const float* __restrict__ bn2) {
    __shared__ float ins[WN1R+1];
    __shared__ float hid[HD];
    int nidx = blockIdx.x;
    int tid = threadIdx.x;
    if (tid < FD) ins[tid] = g_feat[nidx*FD+tid];
    ins[FD+tid] = g_aggm[nidx*HD+tid];
    __syncthreads();
    const float* W = Wn1 + l*WN1R*HD;
    float h = bn1[l*HD+tid];
    #pragma unroll 4
    for (int i = 0; i < WN1R; ++i) h = fmaf(ins[i], W[i*HD+tid], h);
    hid[tid] = silu_f(h);
    __syncthreads();
    if (tid < FD) {
        const float* V = Wn2 + l*HD*FD;
        float o = bn2[l*FD+tid];
        #pragma unroll 4
        for (int k = 0; k < HD; ++k) o = fmaf(hid[k], V[k*FD+tid], o);
        g_feat[nidx*FD+tid] += o;
    }
    if (tid < 3) g_x[nidx*3+tid] += g_aggx[nidx*3+tid];
}

// ------------- output -------------
__global__ void final_k(const float* __restrict__ x_h, const float* __restrict__ x_hv,
                        const int* __restrict__ bound, const float* __restrict__ mask,
                        float* __restrict__ out) {
    int idx = blockIdx.x*blockDim.x + threadIdx.x;
    if (idx >= NNODE*3) return;
    int c = idx % 3;
    int n = idx / 3;
    int r = n % NHY;
    int b = n / (NHY*NS);
    int ba = bound[b*NHY+r];
    float x0 = x_h[idx] + x_hv[(b*NV+ba)*3+c];
    out[idx] = (g_x[idx] - x0) * mask[b*NHY+r];
}

extern "C" void kernel_launch(void* const* d_in, const int* in_sizes, int n_in,
                              void* d_out, int out_size) {
    const float* t     = (const float*)d_in[0];
    const float* x_h   = (const float*)d_in[1];
    const float* x_hv  = (const float*)d_in[2];
    const float* bondm = (const float*)d_in[3];
    const float* emhv  = (const float*)d_in[4];
    const float* emhh  = (const float*)d_in[5];
    const float* amask = (const float*)d_in[6];
    const float* W1    = (const float*)d_in[7];
    const float* b1    = (const float*)d_in[8];
    const float* W2    = (const float*)d_in[9];
    const float* b2    = (const float*)d_in[10];
    const float* Wc1   = (const float*)d_in[11];
    const float* bc1   = (const float*)d_in[12];
    const float* Wc2   = (const float*)d_in[13];
    const float* Wn1   = (const float*)d_in[14];
    const float* bn1   = (const float*)d_in[15];
    const float* Wn2   = (const float*)d_in[16];
    const float* bn2   = (const float*)d_in[17];
    const int* pept    = (const int*)d_in[18];
    const int* labv    = (const int*)d_in[19];
    const int* labh    = (const int*)d_in[20];
    const int* posv    = (const int*)d_in[21];
    const int* posh    = (const int*)d_in[22];
    const int* edges   = (const int*)d_in[23];
    const int* bound   = (const int*)d_in[24];
    float* out = (float*)d_out;

    cudaFuncSetAttribute(edge_k, cudaFuncAttributeMaxDynamicSharedMemorySize, EDGE_SMEM_BYTES);

    csr_k<<<NB, 64>>>(edges, emhh);
    init_k<<<(NNODE+127)/128, 128>>>(x_h, x_hv, bound, labh, posh, pept);
    for (int l = 0; l < NL; ++l) {
        heavycb_k<<<(NB*NV*HD+255)/256, 256>>>(l, W1, labv, posv, pept);
        hcab_k<<<NNODE, HD>>>(l, W1, b1, t);
        edge_k<<<NNODE, 256, EDGE_SMEM_BYTES>>>(l, W1, W2, b2, Wc1, bc1, Wc2,
                                                x_hv, bondm, emhv);
        node_k<<<NNODE, HD>>>(l, Wn1, bn1, Wn2, bn2);
    }
    final_k<<<(NNODE*3+127)/128, 128>>>(x_h, x_hv, bound, amask, out);
}

// round 6
// speedup vs baseline: 1.3263x; 1.3263x over previous
#include <cuda_runtime.h>

#define NB 8
#define NS 4
#define NHY 50
#define NV 200
#define NE 400
#define NL 2
#define FD 79
#define HD 128
#define WN1R 207
#define NNODE (NB*NS*NHY)

// ------------- device scratch (no allocation) -------------
__device__ float g_cA [NNODE*HD];
__device__ float g_cBh[NNODE*HD];
__device__ float g_cBv[NB*NV*HD];
__device__ float g_feat[NNODE*FD];
__device__ float g_x   [NNODE*3];
__device__ float g_aggm[NNODE*HD];
__device__ float g_aggx[NNODE*3];
__device__ int   g_start[NB*(NHY+1)];
__device__ int   g_col[NB*NE];
__device__ float g_em [NB*NE];

__device__ __forceinline__ float silu_f(float x) {
    return __fdividef(x, 1.0f + __expf(-x));
}

// ------------- merged prolog: blocks [0,NB) build CSR, rest do node init -------------
__global__ void prep_k(const int* __restrict__ e, const float* __restrict__ em,
                       const float* __restrict__ x_h, const float* __restrict__ x_hv,
                       const int* __restrict__ bound, const int* __restrict__ labh,
                       const int* __restrict__ posh, const int* __restrict__ pept) {
    __shared__ int cnt[NHY+1];
    if (blockIdx.x < NB) {
        int b = blockIdx.x, t = threadIdx.x;
        if (t <= NHY) cnt[t] = 0;
        __syncthreads();
        if (t < NHY) {
            int c = 0;
            for (int i = 0; i < NE; i++) if (e[(b*NE+i)*2] == t) c++;
            cnt[t+1] = c;
        }
        __syncthreads();
        if (t == 0) for (int i = 0; i < NHY; i++) cnt[i+1] += cnt[i];
        __syncthreads();
        if (t <= NHY) g_start[b*(NHY+1)+t] = cnt[t];
        if (t < NHY) {
            int p = cnt[t];
            for (int i = 0; i < NE; i++) if (e[(b*NE+i)*2] == t) {
                g_col[b*NE+p] = e[(b*NE+i)*2+1];
                g_em [b*NE+p] = em[b*NE+i];
                p++;
            }
        }
    } else {
        int idx = (blockIdx.x - NB)*blockDim.x + threadIdx.x;
        if (idx >= NNODE) return;
        int r = idx % NHY;
        int b = idx / (NHY*NS);
        int ba = bound[b*NHY+r];
        for (int c = 0; c < 3; ++c)
            g_x[idx*3+c] = x_h[idx*3+c] + x_hv[(b*NV+ba)*3+c];
        int lab = labh[b*NHY+r], pos = posh[b*NHY+r];
        int aa = pept[b*15 + pos - 1];
        float* f = g_feat + idx*FD;
        for (int i = 0; i < FD; ++i) f[i] = 0.f;
        f[lab] = 1.f; f[44+aa] = 1.f; f[64+pos-1] = 1.f;
    }
}

// ------------- per layer: heavy cB via one-hot gathers -------------
__global__ void heavycb_k(int l, const float* __restrict__ W1,
                          const int* __restrict__ labv, const int* __restrict__ posv,
                          const int* __restrict__ pept) {
    int idx = blockIdx.x*blockDim.x + threadIdx.x;
    if (idx >= NB*NV*HD) return;
    int k = idx % HD;
    int j = (idx / HD) % NV;
    int b = idx / (HD*NV);
    int lab = labv[b*NV+j];
    int pos = posv[b*NV+j];
    int aa  = pept[b*15 + pos - 1];
    const float* W = W1 + l*161*HD;
    g_cBv[idx] = W[(FD+lab)*HD+k] + W[(FD+44+aa)*HD+k] + W[(FD+64+pos-1)*HD+k];
}

// ------------- per layer: h-node cA (b1+t folded) and cB -------------
__global__ void hcab_k(int l, const float* __restrict__ W1,
                       const float* __restrict__ b1, const float* __restrict__ t) {
    __shared__ float fs[FD];
    int nidx = blockIdx.x;
    int b = nidx / (NHY*NS);
    int tid = threadIdx.x;
    if (tid < FD) fs[tid] = g_feat[nidx*FD+tid];
    __syncthreads();
    const float* W = W1 + l*161*HD;
    float a  = b1[l*HD+tid] + t[b]*W[160*HD+tid];
    float bb = 0.f;
    #pragma unroll 4
    for (int f = 0; f < FD; ++f) {
        float fv = fs[f];
        a  = fmaf(fv, W[f*HD+tid], a);
        bb = fmaf(fv, W[(FD+f)*HD+tid], bb);
    }
    g_cA [nidx*HD+tid] = a;
    g_cBh[nidx*HD+tid] = bb;
}

// ------------- shared GEMM: 4 edges x 4 cols per thread, K=128 -------------
__device__ __forceinline__ void gemm4x4(const float* __restrict__ A, int eg,
                                        const float* __restrict__ Ws, int c,
                                        float acc[16]) {
    #pragma unroll 4
    for (int j = 0; j < HD; j += 4) {
        float4 w0 = *(const float4*)(Ws + (j+0)*HD + c);
        float4 w1 = *(const float4*)(Ws + (j+1)*HD + c);
        float4 w2 = *(const float4*)(Ws + (j+2)*HD + c);
        float4 w3 = *(const float4*)(Ws + (j+3)*HD + c);
        #pragma unroll
        for (int u = 0; u < 4; ++u) {
            float4 a = *(const float4*)(A + (eg + u*8)*132 + j);
            float* ac = acc + u*4;
            ac[0]=fmaf(a.x,w0.x,ac[0]); ac[1]=fmaf(a.x,w0.y,ac[1]); ac[2]=fmaf(a.x,w0.z,ac[2]); ac[3]=fmaf(a.x,w0.w,ac[3]);
            ac[0]=fmaf(a.y,w1.x,ac[0]); ac[1]=fmaf(a.y,w1.y,ac[1]); ac[2]=fmaf(a.y,w1.z,ac[2]); ac[3]=fmaf(a.y,w1.w,ac[3]);
            ac[0]=fmaf(a.z,w2.x,ac[0]); ac[1]=fmaf(a.z,w2.y,ac[1]); ac[2]=fmaf(a.z,w2.z,ac[2]); ac[3]=fmaf(a.z,w2.w,ac[3]);
            ac[0]=fmaf(a.w,w3.x,ac[0]); ac[1]=fmaf(a.w,w3.y,ac[1]); ac[2]=fmaf(a.w,w3.z,ac[2]); ac[3]=fmaf(a.w,w3.w,ac[3]);
        }
    }
}

#define EDGE_SMEM_BYTES (43400*4)

// ------------- edge kernel: 1 block per (b,s,row) -------------
__global__ void __launch_bounds__(256, 1)
edge_k(int l,
       const float* __restrict__ W1,  const float* __restrict__ W2g,
       const float* __restrict__ b2g, const float* __restrict__ Wc1g,
       const float* __restrict__ bc1g,const float* __restrict__ Wc2g,
       const float* __restrict__ x_hv,const float* __restrict__ bondm,
       const float* __restrict__ emhv) {
    extern __shared__ float es[];
    float* W2s   = es;                  // 16384
    float* Wc1s  = es + 16384;          // 16384
    float* b2s   = es + 32768;          // 128
    float* bc1s  = b2s  + HD;           // 128
    float* wc2s  = bc1s + HD;           // 128
    float* w1d   = wc2s + HD;           // 128
    float* w1b   = w1d  + HD;           // 128
    float* cAs   = w1b  + HD;           // 128
    float* m1s   = cAs  + HD;           // 32*132 = 4224
    float* m2s   = m1s  + 32*132;       // 4224
    float* aggm  = m2s  + 32*132;       // 128
    float* cwp   = aggm + HD;           // 32*32 = 1024
    float* diffs = cwp  + 1024;         // 96
    float* dists = diffs+ 96;           // 32
    float* bonds = dists+ 32;           // 32
    float* ems   = bonds+ 32;           // 32
    float* cws   = ems  + 32;           // 32
    float* xrs   = cws  + 32;           // 4
    float* aggx  = xrs  + 4;            // 4
    int*   colss = (int*)(aggx + 4);    // 32

    int tid = threadIdx.x;
    int blk = blockIdx.x;
    int r = blk % NHY;
    int s = (blk / NHY) % NS;
    int b = blk / (NHY*NS);
    int nidx = (b*NS+s)*NHY + r;

    const float* W2p  = W2g  + l*HD*HD;
    const float* Wc1p = Wc1g + l*HD*HD;
    for (int i = tid; i < HD*HD/4; i += 256) {
        ((float4*)W2s)[i]  = ((const float4*)W2p)[i];
        ((float4*)Wc1s)[i] = ((const float4*)Wc1p)[i];
    }
    if (tid < HD) {
        b2s [tid] = b2g [l*HD+tid];
        bc1s[tid] = bc1g[l*HD+tid];
        wc2s[tid] = Wc2g[l*HD+tid];
        w1d [tid] = W1[(l*161+158)*HD+tid];
        w1b [tid] = W1[(l*161+159)*HD+tid];
        cAs [tid] = g_cA[nidx*HD+tid];
        aggm[tid] = 0.f;
    }
    if (tid < 3) { xrs[tid] = g_x[nidx*3+tid]; aggx[tid] = 0.f; }
    int hh0   = g_start[b*(NHY+1)+r];
    int hhcnt = g_start[b*(NHY+1)+r+1] - hh0;
    int ne = NV + hhcnt;
    int ntile = (ne + 31) >> 5;
    __syncthreads();

    for (int tile = 0; tile < ntile; ++tile) {
        // --- stage 0: per-edge scalars ---
        if (tid < 32) {
            int e = tile*32 + tid;
            int col = NHY; float bond = 0.f, em = 0.f;
            float d0 = 0.f, d1 = 0.f, d2 = 0.f;
            if (e < NV) {
                col  = NHY + e;
                bond = bondm[(b*NHY+r)*NV + e];
                em   = emhv [(b*NHY+r)*NV + e];
            } else if (e < ne) {
                int ii = hh0 + (e - NV);
                col = g_col[b*NE+ii];
                em  = g_em [b*NE+ii];
            }
            if (e < ne) {
                const float* xc = (col >= NHY) ? (x_hv + (b*NV + (col-NHY))*3)
                                               : (g_x + ((b*NS+s)*NHY+col)*3);
                d0 = xrs[0]-xc[0]; d1 = xrs[1]-xc[1]; d2 = xrs[2]-xc[2];
            }
            diffs[tid*3+0]=d0; diffs[tid*3+1]=d1; diffs[tid*3+2]=d2;
            dists[tid] = sqrtf(d0*d0 + d1*d1 + d2*d2);
            bonds[tid] = bond; ems[tid] = em; colss[tid] = col;
        }
        __syncthreads();
        // --- stage 1: m1 = silu(cA + cB[col] + d*wd + bond*wb) ---
        #pragma unroll
        for (int rep = 0; rep < 4; ++rep) {
            int q = rep*256 + tid;
            int e = q >> 5;
            int k4 = (q & 31) << 2;
            int col = colss[e];
            const float* cb = (col >= NHY) ? (g_cBv + (b*NV + (col-NHY))*HD)
                                           : (g_cBh + (((b*NS+s)*NHY)+col)*HD);
            float4 cv = *(const float4*)(cb + k4);
            float dd = dists[e], bo = bonds[e];
            float4 o;
            o.x = silu_f(cAs[k4+0] + cv.x + dd*w1d[k4+0] + bo*w1b[k4+0]);
            o.y = silu_f(cAs[k4+1] + cv.y + dd*w1d[k4+1] + bo*w1b[k4+1]);
            o.z = silu_f(cAs[k4+2] + cv.z + dd*w1d[k4+2] + bo*w1b[k4+2]);
            o.w = silu_f(cAs[k4+3] + cv.w + dd*w1d[k4+3] + bo*w1b[k4+3]);
            *(float4*)(m1s + e*132 + k4) = o;
        }
        __syncthreads();
        int eg = tid & 7, cg = tid >> 3, c = cg*4;
        // --- stage 2: m2 = silu(m1@W2 + b2) * emask ---
        {
            float acc[16];
            #pragma unroll
            for (int u = 0; u < 4; ++u)
                for (int i = 0; i < 4; ++i) acc[u*4+i] = b2s[c+i];
            gemm4x4(m1s, eg, W2s, c, acc);
            #pragma unroll
            for (int u = 0; u < 4; ++u) {
                int e = eg + u*8;
                float em = ems[e];
                float4 v;
                v.x = silu_f(acc[u*4+0])*em; v.y = silu_f(acc[u*4+1])*em;
                v.z = silu_f(acc[u*4+2])*em; v.w = silu_f(acc[u*4+3])*em;
                *(float4*)(m2s + e*132 + c) = v;
            }
        }
        __syncthreads();
        // --- stage 3: cw = silu(m2@Wc1 + bc1) . Wc2 ---
        {
            float acc[16];
            #pragma unroll
            for (int u = 0; u < 4; ++u)
                for (int i = 0; i < 4; ++i) acc[u*4+i] = bc1s[c+i];
            gemm4x4(m2s, eg, Wc1s, c, acc);
            #pragma unroll
            for (int u = 0; u < 4; ++u) {
                int e = eg + u*8;
                float cw = 0.f;
                #pragma unroll
                for (int i = 0; i < 4; ++i) cw += silu_f(acc[u*4+i]) * wc2s[c+i];
                cwp[e*32+cg] = cw;
            }
        }
        __syncthreads();
        // --- stage 4a: aggregate m2, reduce cw partials ---
        if (tid < HD) {
            float a = aggm[tid];
            #pragma unroll
            for (int e = 0; e < 32; ++e) a += m2s[e*132+tid];
            aggm[tid] = a;
        } else if (tid < HD + 32) {
            int e = tid - HD;
            float sum = 0.f;
            #pragma unroll
            for (int i = 0; i < 32; ++i) sum += cwp[e*32+i];
            cws[e] = sum;
        }
        __syncthreads();
        // --- stage 4b: aggregate diff*cw ---
        if (tid < 3) {
            float a = aggx[tid];
            #pragma unroll
            for (int e = 0; e < 32; ++e) a += diffs[e*3+tid]*cws[e];
            aggx[tid] = a;
        }
        __syncthreads();
    }
    if (tid < HD) g_aggm[nidx*HD+tid] = aggm[tid];
    if (tid < 3)  g_aggx[nidx*3+tid]  = aggx[tid];
}

// ------------- node update -------------
__global__ void node_k(int l, const float* __restrict__ Wn1, const float* __restrict__ bn1,
                       const float* __restrict__ Wn2, const float* __restrict__ bn2) {
    __shared__ float ins[WN1R+1];
    __shared__ float hid[HD];
    int nidx = blockIdx.x;
    int tid = threadIdx.x;
    if (tid < FD) ins[tid] = g_feat[nidx*FD+tid];
    ins[FD+tid] = g_aggm[nidx*HD+tid];
    __syncthreads();
    const float* W = Wn1 + l*WN1R*HD;
    float h = bn1[l*HD+tid];
    #pragma unroll 4
    for (int i = 0; i < WN1R; ++i) h = fmaf(ins[i], W[i*HD+tid], h);
    hid[tid] = silu_f(h);
    __syncthreads();
    if (tid < FD) {
        const float* V = Wn2 + l*HD*FD;
        float o = bn2[l*FD+tid];
        #pragma unroll 4
        for (int k = 0; k < HD; ++k) o = fmaf(hid[k], V[k*FD+tid], o);
        g_feat[nidx*FD+tid] += o;
    }
    if (tid < 3) g_x[nidx*3+tid] += g_aggx[nidx*3+tid];
}

// ------------- output -------------
__global__ void final_k(const float* __restrict__ x_h, const float* __restrict__ x_hv,
                        const int* __restrict__ bound, const float* __restrict__ mask,
                        float* __restrict__ out) {
    int idx = blockIdx.x*blockDim.x + threadIdx.x;
    if (idx >= NNODE*3) return;
    int c = idx % 3;
    int n = idx / 3;
    int r = n % NHY;
    int b = n / (NHY*NS);
    int ba = bound[b*NHY+r];
    float x0 = x_h[idx] + x_hv[(b*NV+ba)*3+c];
    out[idx] = (g_x[idx] - x0) * mask[b*NHY+r];
}

extern "C" void kernel_launch(void* const* d_in, const int* in_sizes, int n_in,
                              void* d_out, int out_size) {
    const float* t     = (const float*)d_in[0];
    const float* x_h   = (const float*)d_in[1];
    const float* x_hv  = (const float*)d_in[2];
    const float* bondm = (const float*)d_in[3];
    const float* emhv  = (const float*)d_in[4];
    const float* emhh  = (const float*)d_in[5];
    const float* amask = (const float*)d_in[6];
    const float* W1    = (const float*)d_in[7];
    const float* b1    = (const float*)d_in[8];
    const float* W2    = (const float*)d_in[9];
    const float* b2    = (const float*)d_in[10];
    const float* Wc1   = (const float*)d_in[11];
    const float* bc1   = (const float*)d_in[12];
    const float* Wc2   = (const float*)d_in[13];
    const float* Wn1   = (const float*)d_in[14];
    const float* bn1   = (const float*)d_in[15];
    const float* Wn2   = (const float*)d_in[16];
    const float* bn2   = (const float*)d_in[17];
    const int* pept    = (const int*)d_in[18];
    const int* labv    = (const int*)d_in[19];
    const int* labh    = (const int*)d_in[20];
    const int* posv    = (const int*)d_in[21];
    const int* posh    = (const int*)d_in[22];
    const int* edges   = (const int*)d_in[23];
    const int* bound   = (const int*)d_in[24];
    float* out = (float*)d_out;

    cudaFuncSetAttribute(edge_k, cudaFuncAttributeMaxDynamicSharedMemorySize, EDGE_SMEM_BYTES);

    // launch order tuned so the ncu window (-s 5 -c 1, 2 harness launches ahead)
    // lands on edge_k: prep(0), heavycb(1), hcab(2), edge(3) <- captured
    prep_k<<<NB + (NNODE+127)/128, 128>>>(edges, emhh, x_h, x_hv, bound, labh, posh, pept);
    for (int l = 0; l < NL; ++l) {
        heavycb_k<<<(NB*NV*HD+255)/256, 256>>>(l, W1, labv, posv, pept);
        hcab_k<<<NNODE, HD>>>(l, W1, b1, t);
        edge_k<<<NNODE, 256, EDGE_SMEM_BYTES>>>(l, W1, W2, b2, Wc1, bc1, Wc2,
                                                x_hv, bondm, emhv);
        node_k<<<NNODE, HD>>>(l, Wn1, bn1, Wn2, bn2);
    }
    final_k<<<(NNODE*3+127)/128, 128>>>(x_h, x_hv, bound, amask, out);
}

// round 7
// speedup vs baseline: 1.3460x; 1.0149x over previous
#include <cuda_runtime.h>

#define NB 8
#define NS 4
#define NHY 50
#define NV 200
#define NE 400
#define NL 2
#define FD 79
#define HD 128
#define WN1R 207
#define NNODE (NB*NS*NHY)

#define ETILE 64          // edges per tile
#define ETHREADS 512      // edge_k block size

// ------------- device scratch (no allocation) -------------
__device__ float g_cA [NNODE*HD];
__device__ float g_cBh[NNODE*HD];
__device__ float g_cBv[NB*NV*HD];
__device__ float g_feat[NNODE*FD];
__device__ float g_x   [NNODE*3];
__device__ float g_aggm[NNODE*HD];
__device__ float g_aggx[NNODE*3];
__device__ int   g_start[NB*(NHY+1)];
__device__ int   g_col[NB*NE];
__device__ float g_em [NB*NE];

__device__ __forceinline__ float silu_f(float x) {
    return __fdividef(x, 1.0f + __expf(-x));
}

// ------------- merged prolog: blocks [0,NB) build CSR, rest do node init -------------
__global__ void prep_k(const int* __restrict__ e, const float* __restrict__ em,
                       const float* __restrict__ x_h, const float* __restrict__ x_hv,
                       const int* __restrict__ bound, const int* __restrict__ labh,
                       const int* __restrict__ posh, const int* __restrict__ pept) {
    __shared__ int cnt[NHY+1];
    if (blockIdx.x < NB) {
        int b = blockIdx.x, t = threadIdx.x;
        if (t <= NHY) cnt[t] = 0;
        __syncthreads();
        if (t < NHY) {
            int c = 0;
            for (int i = 0; i < NE; i++) if (e[(b*NE+i)*2] == t) c++;
            cnt[t+1] = c;
        }
        __syncthreads();
        if (t == 0) for (int i = 0; i < NHY; i++) cnt[i+1] += cnt[i];
        __syncthreads();
        if (t <= NHY) g_start[b*(NHY+1)+t] = cnt[t];
        if (t < NHY) {
            int p = cnt[t];
            for (int i = 0; i < NE; i++) if (e[(b*NE+i)*2] == t) {
                g_col[b*NE+p] = e[(b*NE+i)*2+1];
                g_em [b*NE+p] = em[b*NE+i];
                p++;
            }
        }
    } else {
        int idx = (blockIdx.x - NB)*blockDim.x + threadIdx.x;
        if (idx >= NNODE) return;
        int r = idx % NHY;
        int b = idx / (NHY*NS);
        int ba = bound[b*NHY+r];
        for (int c = 0; c < 3; ++c)
            g_x[idx*3+c] = x_h[idx*3+c] + x_hv[(b*NV+ba)*3+c];
        int lab = labh[b*NHY+r], pos = posh[b*NHY+r];
        int aa = pept[b*15 + pos - 1];
        float* f = g_feat + idx*FD;
        for (int i = 0; i < FD; ++i) f[i] = 0.f;
        f[lab] = 1.f; f[44+aa] = 1.f; f[64+pos-1] = 1.f;
    }
}

// ------------- per layer: heavy cB via one-hot gathers -------------
__global__ void heavycb_k(int l, const float* __restrict__ W1,
                          const int* __restrict__ labv, const int* __restrict__ posv,
                          const int* __restrict__ pept) {
    int idx = blockIdx.x*blockDim.x + threadIdx.x;
    if (idx >= NB*NV*HD) return;
    int k = idx % HD;
    int j = (idx / HD) % NV;
    int b = idx / (HD*NV);
    int lab = labv[b*NV+j];
    int pos = posv[b*NV+j];
    int aa  = pept[b*15 + pos - 1];
    const float* W = W1 + l*161*HD;
    g_cBv[idx] = W[(FD+lab)*HD+k] + W[(FD+44+aa)*HD+k] + W[(FD+64+pos-1)*HD+k];
}

// ------------- per layer: h-node cA (b1+t folded) and cB -------------
__global__ void hcab_k(int l, const float* __restrict__ W1,
                       const float* __restrict__ b1, const float* __restrict__ t) {
    __shared__ float fs[FD];
    int nidx = blockIdx.x;
    int b = nidx / (NHY*NS);
    int tid = threadIdx.x;
    if (tid < FD) fs[tid] = g_feat[nidx*FD+tid];
    __syncthreads();
    const float* W = W1 + l*161*HD;
    float a  = b1[l*HD+tid] + t[b]*W[160*HD+tid];
    float bb = 0.f;
    #pragma unroll 4
    for (int f = 0; f < FD; ++f) {
        float fv = fs[f];
        a  = fmaf(fv, W[f*HD+tid], a);
        bb = fmaf(fv, W[(FD+f)*HD+tid], bb);
    }
    g_cA [nidx*HD+tid] = a;
    g_cBh[nidx*HD+tid] = bb;
}

// ------------- shared GEMM: 4 edges x 4 cols per thread, K=128 -------------
// edges e = eg + u*16 (eg in 0..15), cols c..c+3 (c = (tid>>4)*4)
__device__ __forceinline__ void gemm4x4(const float* __restrict__ A, int eg,
                                        const float* __restrict__ Ws, int c,
                                        float acc[16]) {
    #pragma unroll 4
    for (int j = 0; j < HD; j += 4) {
        float4 w0 = *(const float4*)(Ws + (j+0)*HD + c);
        float4 w1 = *(const float4*)(Ws + (j+1)*HD + c);
        float4 w2 = *(const float4*)(Ws + (j+2)*HD + c);
        float4 w3 = *(const float4*)(Ws + (j+3)*HD + c);
        #pragma unroll
        for (int u = 0; u < 4; ++u) {
            float4 a = *(const float4*)(A + (eg + u*16)*132 + j);
            float* ac = acc + u*4;
            ac[0]=fmaf(a.x,w0.x,ac[0]); ac[1]=fmaf(a.x,w0.y,ac[1]); ac[2]=fmaf(a.x,w0.z,ac[2]); ac[3]=fmaf(a.x,w0.w,ac[3]);
            ac[0]=fmaf(a.y,w1.x,ac[0]); ac[1]=fmaf(a.y,w1.y,ac[1]); ac[2]=fmaf(a.y,w1.z,ac[2]); ac[3]=fmaf(a.y,w1.w,ac[3]);
            ac[0]=fmaf(a.z,w2.x,ac[0]); ac[1]=fmaf(a.z,w2.y,ac[1]); ac[2]=fmaf(a.z,w2.z,ac[2]); ac[3]=fmaf(a.z,w2.w,ac[3]);
            ac[0]=fmaf(a.w,w3.x,ac[0]); ac[1]=fmaf(a.w,w3.y,ac[1]); ac[2]=fmaf(a.w,w3.z,ac[2]); ac[3]=fmaf(a.w,w3.w,ac[3]);
        }
    }
}

// smem float layout (64-edge tiles)
#define OFF_W2    0
#define OFF_WC1   16384
#define OFF_B2    32768
#define OFF_BC1   (OFF_B2 + HD)
#define OFF_WC2   (OFF_BC1 + HD)
#define OFF_W1D   (OFF_WC2 + HD)
#define OFF_W1B   (OFF_W1D + HD)
#define OFF_CA    (OFF_W1B + HD)
#define OFF_M1    (OFF_CA + HD)
#define OFF_M2    (OFF_M1 + ETILE*132)
#define OFF_AGGM  (OFF_M2 + ETILE*132)
#define OFF_AGGP  (OFF_AGGM + HD)
#define OFF_CWP   (OFF_AGGP + 4*HD)
#define OFF_DIFF  (OFF_CWP + ETILE*32)
#define OFF_DIST  (OFF_DIFF + ETILE*3)
#define OFF_BOND  (OFF_DIST + ETILE)
#define OFF_EMS   (OFF_BOND + ETILE)
#define OFF_CWS   (OFF_EMS + ETILE)
#define OFF_XR    (OFF_CWS + ETILE)
#define OFF_AGGX  (OFF_XR + 4)
#define OFF_COLS  (OFF_AGGX + 4)
#define EDGE_SMEM_FLOATS (OFF_COLS + ETILE)
#define EDGE_SMEM_BYTES (EDGE_SMEM_FLOATS*4)

// ------------- edge kernel: 1 block per (b,s,row), 512 threads -------------
__global__ void __launch_bounds__(ETHREADS, 1)
edge_k(int l,
       const float* __restrict__ W1,  const float* __restrict__ W2g,
       const float* __restrict__ b2g, const float* __restrict__ Wc1g,
       const float* __restrict__ bc1g,const float* __restrict__ Wc2g,
       const float* __restrict__ x_hv,const float* __restrict__ bondm,
       const float* __restrict__ emhv) {
    extern __shared__ float es[];
    float* W2s   = es + OFF_W2;
    float* Wc1s  = es + OFF_WC1;
    float* b2s   = es + OFF_B2;
    float* bc1s  = es + OFF_BC1;
    float* wc2s  = es + OFF_WC2;
    float* w1d   = es + OFF_W1D;
    float* w1b   = es + OFF_W1B;
    float* cAs   = es + OFF_CA;
    float* m1s   = es + OFF_M1;
    float* m2s   = es + OFF_M2;
    float* aggm  = es + OFF_AGGM;
    float* aggp  = es + OFF_AGGP;
    float* cwp   = es + OFF_CWP;
    float* diffs = es + OFF_DIFF;
    float* dists = es + OFF_DIST;
    float* bonds = es + OFF_BOND;
    float* ems   = es + OFF_EMS;
    float* cws   = es + OFF_CWS;
    float* xrs   = es + OFF_XR;
    float* aggx  = es + OFF_AGGX;
    int*   colss = (int*)(es + OFF_COLS);

    int tid = threadIdx.x;
    int blk = blockIdx.x;
    int r = blk % NHY;
    int s = (blk / NHY) % NS;
    int b = blk / (NHY*NS);
    int nidx = (b*NS+s)*NHY + r;

    const float* W2p  = W2g  + l*HD*HD;
    const float* Wc1p = Wc1g + l*HD*HD;
    for (int i = tid; i < HD*HD/4; i += ETHREADS) {
        ((float4*)W2s)[i]  = ((const float4*)W2p)[i];
        ((float4*)Wc1s)[i] = ((const float4*)Wc1p)[i];
    }
    if (tid < HD) {
        b2s [tid] = b2g [l*HD+tid];
        bc1s[tid] = bc1g[l*HD+tid];
        wc2s[tid] = Wc2g[l*HD+tid];
        w1d [tid] = W1[(l*161+158)*HD+tid];
        w1b [tid] = W1[(l*161+159)*HD+tid];
        cAs [tid] = g_cA[nidx*HD+tid];
        aggm[tid] = 0.f;
    }
    if (tid < 3) { xrs[tid] = g_x[nidx*3+tid]; aggx[tid] = 0.f; }
    int hh0   = g_start[b*(NHY+1)+r];
    int hhcnt = g_start[b*(NHY+1)+r+1] - hh0;
    int ne = NV + hhcnt;
    int ntile = (ne + ETILE - 1) / ETILE;
    __syncthreads();

    int eg = tid & 15, cg = tid >> 4, c = cg*4;

    for (int tile = 0; tile < ntile; ++tile) {
        // --- stage 0: per-edge scalars ---
        if (tid < ETILE) {
            int e = tile*ETILE + tid;
            int col = NHY; float bond = 0.f, em = 0.f;
            float d0 = 0.f, d1 = 0.f, d2 = 0.f;
            if (e < NV) {
                col  = NHY + e;
                bond = bondm[(b*NHY+r)*NV + e];
                em   = emhv [(b*NHY+r)*NV + e];
            } else if (e < ne) {
                int ii = hh0 + (e - NV);
                col = g_col[b*NE+ii];
                em  = g_em [b*NE+ii];
            }
            if (e < ne) {
                const float* xc = (col >= NHY) ? (x_hv + (b*NV + (col-NHY))*3)
                                               : (g_x + ((b*NS+s)*NHY+col)*3);
                d0 = xrs[0]-xc[0]; d1 = xrs[1]-xc[1]; d2 = xrs[2]-xc[2];
            }
            diffs[tid*3+0]=d0; diffs[tid*3+1]=d1; diffs[tid*3+2]=d2;
            dists[tid] = sqrtf(d0*d0 + d1*d1 + d2*d2);
            bonds[tid] = bond; ems[tid] = em; colss[tid] = col;
        }
        __syncthreads();
        // --- stage 1: m1 = silu(cA + cB[col] + d*wd + bond*wb) ---
        #pragma unroll
        for (int rep = 0; rep < 4; ++rep) {
            int q = rep*ETHREADS + tid;
            int e = q >> 5;
            int k4 = (q & 31) << 2;
            int col = colss[e];
            const float* cb = (col >= NHY) ? (g_cBv + (b*NV + (col-NHY))*HD)
                                           : (g_cBh + (((b*NS+s)*NHY)+col)*HD);
            float4 cv = *(const float4*)(cb + k4);
            float dd = dists[e], bo = bonds[e];
            float4 o;
            o.x = silu_f(cAs[k4+0] + cv.x + dd*w1d[k4+0] + bo*w1b[k4+0]);
            o.y = silu_f(cAs[k4+1] + cv.y + dd*w1d[k4+1] + bo*w1b[k4+1]);
            o.z = silu_f(cAs[k4+2] + cv.z + dd*w1d[k4+2] + bo*w1b[k4+2]);
            o.w = silu_f(cAs[k4+3] + cv.w + dd*w1d[k4+3] + bo*w1b[k4+3]);
            *(float4*)(m1s + e*132 + k4) = o;
        }
        __syncthreads();
        // --- stage 2: m2 = silu(m1@W2 + b2) * emask ---
        {
            float acc[16];
            #pragma unroll
            for (int u = 0; u < 4; ++u)
                for (int i = 0; i < 4; ++i) acc[u*4+i] = b2s[c+i];
            gemm4x4(m1s, eg, W2s, c, acc);
            #pragma unroll
            for (int u = 0; u < 4; ++u) {
                int e = eg + u*16;
                float em = ems[e];
                float4 v;
                v.x = silu_f(acc[u*4+0])*em; v.y = silu_f(acc[u*4+1])*em;
                v.z = silu_f(acc[u*4+2])*em; v.w = silu_f(acc[u*4+3])*em;
                *(float4*)(m2s + e*132 + c) = v;
            }
        }
        __syncthreads();
        // --- stage 3: cw = silu(m2@Wc1 + bc1) . Wc2 ---
        {
            float acc[16];
            #pragma unroll
            for (int u = 0; u < 4; ++u)
                for (int i = 0; i < 4; ++i) acc[u*4+i] = bc1s[c+i];
            gemm4x4(m2s, eg, Wc1s, c, acc);
            #pragma unroll
            for (int u = 0; u < 4; ++u) {
                int e = eg + u*16;
                float cw = 0.f;
                #pragma unroll
                for (int i = 0; i < 4; ++i) cw += silu_f(acc[u*4+i]) * wc2s[c+i];
                cwp[e*32+cg] = cw;
            }
        }
        __syncthreads();
        // --- stage 4a: partial m2 aggregation (4 groups of 16 edges) ---
        {
            int g = tid >> 7;          // 0..3
            int colx = tid & 127;
            float a = 0.f;
            #pragma unroll
            for (int i = 0; i < 16; ++i) a += m2s[(g*16+i)*132 + colx];
            aggp[g*HD + colx] = a;
        }
        __syncthreads();
        // --- stage 4b: combine partials; reduce cw ---
        if (tid < HD) {
            aggm[tid] += aggp[tid] + aggp[HD+tid] + aggp[2*HD+tid] + aggp[3*HD+tid];
        } else if (tid < HD + ETILE) {
            int e = tid - HD;
            float sum = 0.f;
            #pragma unroll
            for (int i = 0; i < 32; ++i) sum += cwp[e*32+i];
            cws[e] = sum;
        }
        __syncthreads();
        // --- stage 4c: aggregate diff*cw ---
        if (tid < 3) {
            float a = aggx[tid];
            #pragma unroll
            for (int e = 0; e < ETILE; ++e) a += diffs[e*3+tid]*cws[e];
            aggx[tid] = a;
        }
        __syncthreads();
    }
    if (tid < HD) g_aggm[nidx*HD+tid] = aggm[tid];
    if (tid < 3)  g_aggx[nidx*3+tid]  = aggx[tid];
}

// ------------- node update -------------
__global__ void node_k(int l, const float* __restrict__ Wn1, const float* __restrict__ bn1,
                       const float* __restrict__ Wn2, const float* __restrict__ bn2) {
    __shared__ float ins[WN1R+1];
    __shared__ float hid[HD];
    int nidx = blockIdx.x;
    int tid = threadIdx.x;
    if (tid < FD) ins[tid] = g_feat[nidx*FD+tid];
    ins[FD+tid] = g_aggm[nidx*HD+tid];
    __syncthreads();
    const float* W = Wn1 + l*WN1R*HD;
    float h = bn1[l*HD+tid];
    #pragma unroll 4
    for (int i = 0; i < WN1R; ++i) h = fmaf(ins[i], W[i*HD+tid], h);
    hid[tid] = silu_f(h);
    __syncthreads();
    if (tid < FD) {
        const float* V = Wn2 + l*HD*FD;
        float o = bn2[l*FD+tid];
        #pragma unroll 4
        for (int k = 0; k < HD; ++k) o = fmaf(hid[k], V[k*FD+tid], o);
        g_feat[nidx*FD+tid] += o;
    }
    if (tid < 3) g_x[nidx*3+tid] += g_aggx[nidx*3+tid];
}

// ------------- output -------------
__global__ void final_k(const float* __restrict__ x_h, const float* __restrict__ x_hv,
                        const int* __restrict__ bound, const float* __restrict__ mask,
                        float* __restrict__ out) {
    int idx = blockIdx.x*blockDim.x + threadIdx.x;
    if (idx >= NNODE*3) return;
    int c = idx % 3;
    int n = idx / 3;
    int r = n % NHY;
    int b = n / (NHY*NS);
    int ba = bound[b*NHY+r];
    float x0 = x_h[idx] + x_hv[(b*NV+ba)*3+c];
    out[idx] = (g_x[idx] - x0) * mask[b*NHY+r];
}

extern "C" void kernel_launch(void* const* d_in, const int* in_sizes, int n_in,
                              void* d_out, int out_size) {
    const float* t     = (const float*)d_in[0];
    const float* x_h   = (const float*)d_in[1];
    const float* x_hv  = (const float*)d_in[2];
    const float* bondm = (const float*)d_in[3];
    const float* emhv  = (const float*)d_in[4];
    const float* emhh  = (const float*)d_in[5];
    const float* amask = (const float*)d_in[6];
    const float* W1    = (const float*)d_in[7];
    const float* b1    = (const float*)d_in[8];
    const float* W2    = (const float*)d_in[9];
    const float* b2    = (const float*)d_in[10];
    const float* Wc1   = (const float*)d_in[11];
    const float* bc1   = (const float*)d_in[12];
    const float* Wc2   = (const float*)d_in[13];
    const float* Wn1   = (const float*)d_in[14];
    const float* bn1   = (const float*)d_in[15];
    const float* Wn2   = (const float*)d_in[16];
    const float* bn2   = (const float*)d_in[17];
    const int* pept    = (const int*)d_in[18];
    const int* labv    = (const int*)d_in[19];
    const int* labh    = (const int*)d_in[20];
    const int* posv    = (const int*)d_in[21];
    const int* posh    = (const int*)d_in[22];
    const int* edges   = (const int*)d_in[23];
    const int* bound   = (const int*)d_in[24];
    float* out = (float*)d_out;

    cudaFuncSetAttribute(edge_k, cudaFuncAttributeMaxDynamicSharedMemorySize, EDGE_SMEM_BYTES);

    // launch order keeps the ncu window (-s 5 -c 1) on edge_k:
    // prep(0), heavycb(1), hcab(2), edge(3) <- captured
    prep_k<<<NB + (NNODE+127)/128, 128>>>(edges, emhh, x_h, x_hv, bound, labh, posh, pept);
    for (int l = 0; l < NL; ++l) {
        heavycb_k<<<(NB*NV*HD+255)/256, 256>>>(l, W1, labv, posv, pept);
        hcab_k<<<NNODE, HD>>>(l, W1, b1, t);
        edge_k<<<NNODE, ETHREADS, EDGE_SMEM_BYTES>>>(l, W1, W2, b2, Wc1, bc1, Wc2,
                                                     x_hv, bondm, emhv);
        node_k<<<NNODE, HD>>>(l, Wn1, bn1, Wn2, bn2);
    }
    final_k<<<(NNODE*3+127)/128, 128>>>(x_h, x_hv, bound, amask, out);
}

// round 8
// speedup vs baseline: 2.9255x; 2.1734x over previous
#include <cuda_runtime.h>
#include <cstdint>

#define NB 8
#define NS 4
#define NHY 50
#define NV 200
#define NE 400
#define NL 2
#define FD 79
#define HD 128
#define WN1R 207
#define NNODE (NB*NS*NHY)

#define ETILE 64
#define ETHREADS 512

// ------------- device scratch (no allocation) -------------
__device__ float g_cA [NNODE*HD];
__device__ float g_cBh[NNODE*HD];
__device__ float g_cBv[NB*NV*HD];
__device__ float g_feat[NNODE*FD];
__device__ float g_x   [NNODE*3];
__device__ float g_aggm[NNODE*HD];
__device__ float g_aggx[NNODE*3];
__device__ int   g_start[NB*(NHY+1)];
__device__ int   g_col[NB*NE];
__device__ float g_em [NB*NE];
__device__ float g_W2p [NL*HD*HD];   // W2 in tf32 fragment order
__device__ float g_Wc1p[NL*HD*HD];   // Wc1 in tf32 fragment order

__device__ __forceinline__ float silu_f(float x) {
    return __fdividef(x, 1.0f + __expf(-x));
}
__device__ __forceinline__ uint32_t tf32r(float x) {
    uint32_t r; asm("cvt.rna.tf32.f32 %0, %1;" : "=r"(r) : "f"(x)); return r;
}
__device__ __forceinline__ float tf32f(float x) { return __uint_as_float(tf32r(x)); }

__device__ __forceinline__ void mma_tf32(float acc[4],
                                         uint32_t a0, uint32_t a1, uint32_t a2, uint32_t a3,
                                         uint32_t b0, uint32_t b1) {
    asm("mma.sync.aligned.m16n8k8.row.col.f32.tf32.tf32.f32 "
        "{%0,%1,%2,%3},{%4,%5,%6,%7},{%8,%9},{%0,%1,%2,%3};"
        : "+f"(acc[0]), "+f"(acc[1]), "+f"(acc[2]), "+f"(acc[3])
        : "r"(a0), "r"(a1), "r"(a2), "r"(a3), "r"(b0), "r"(b1));
}

// ------------- merged prolog: blocks [0,NB) build CSR, rest do node init -------------
__global__ void prep_k(const int* __restrict__ e, const float* __restrict__ em,
                       const float* __restrict__ x_h, const float* __restrict__ x_hv,
                       const int* __restrict__ bound, const int* __restrict__ labh,
                       const int* __restrict__ posh, const int* __restrict__ pept) {
    __shared__ int cnt[NHY+1];
    if (blockIdx.x < NB) {
        int b = blockIdx.x, t = threadIdx.x;
        if (t <= NHY) cnt[t] = 0;
        __syncthreads();
        if (t < NHY) {
            int c = 0;
            for (int i = 0; i < NE; i++) if (e[(b*NE+i)*2] == t) c++;
            cnt[t+1] = c;
        }
        __syncthreads();
        if (t == 0) for (int i = 0; i < NHY; i++) cnt[i+1] += cnt[i];
        __syncthreads();
        if (t <= NHY) g_start[b*(NHY+1)+t] = cnt[t];
        if (t < NHY) {
            int p = cnt[t];
            for (int i = 0; i < NE; i++) if (e[(b*NE+i)*2] == t) {
                g_col[b*NE+p] = e[(b*NE+i)*2+1];
                g_em [b*NE+p] = em[b*NE+i];
                p++;
            }
        }
    } else {
        int idx = (blockIdx.x - NB)*blockDim.x + threadIdx.x;
        if (idx >= NNODE) return;
        int r = idx % NHY;
        int b = idx / (NHY*NS);
        int ba = bound[b*NHY+r];
        for (int c = 0; c < 3; ++c)
            g_x[idx*3+c] = x_h[idx*3+c] + x_hv[(b*NV+ba)*3+c];
        int lab = labh[b*NHY+r], pos = posh[b*NHY+r];
        int aa = pept[b*15 + pos - 1];
        float* f = g_feat + idx*FD;
        for (int i = 0; i < FD; ++i) f[i] = 0.f;
        f[lab] = 1.f; f[44+aa] = 1.f; f[64+pos-1] = 1.f;
    }
}

// ------------- weight permute to mma fragment order (both layers, both matrices) -------------
// layout: idx = (kt*16 + nt)*64 + lane*2 + bsel ; value = W[kt*8 + t + 4*bsel][nt*8 + g]
__global__ void wperm_k(const float* __restrict__ W2, const float* __restrict__ Wc1) {
    int idx = blockIdx.x*blockDim.x + threadIdx.x;   // 0 .. 4*16384-1
    if (idx >= 4*HD*HD) return;
    int m = idx >> 14;         // 0..3 : layer = m>>1, which = m&1
    int j = idx & 16383;
    int q  = j & 63;
    int nt = (j >> 6) & 15;
    int kt = j >> 10;
    int lane = q >> 1, bsel = q & 1;
    int t = lane & 3, g = lane >> 2;
    int k = kt*8 + t + 4*bsel;
    int n = nt*8 + g;
    int l = m >> 1;
    const float* src = (m & 1) ? Wc1 : W2;
    float v = src[(l*HD + k)*HD + n];
    float* dst = (m & 1) ? g_Wc1p : g_W2p;
    dst[l*HD*HD + j] = __uint_as_float(tf32r(v));
}

// ------------- per layer merged: blocks [0,NNODE) h-node cA/cB, rest heavy cB -------------
__global__ void nodecb_k(int l, const float* __restrict__ W1,
                         const float* __restrict__ b1, const float* __restrict__ t,
                         const int* __restrict__ labv, const int* __restrict__ posv,
                         const int* __restrict__ pept) {
    __shared__ float fs[FD];
    if (blockIdx.x < NNODE) {
        int nidx = blockIdx.x;
        int b = nidx / (NHY*NS);
        int tid = threadIdx.x;
        if (tid < FD) fs[tid] = g_feat[nidx*FD+tid];
        __syncthreads();
        const float* W = W1 + l*161*HD;
        float a  = b1[l*HD+tid] + t[b]*W[160*HD+tid];
        float bb = 0.f;
        #pragma unroll 4
        for (int f = 0; f < FD; ++f) {
            float fv = fs[f];
            a  = fmaf(fv, W[f*HD+tid], a);
            bb = fmaf(fv, W[(FD+f)*HD+tid], bb);
        }
        g_cA [nidx*HD+tid] = a;
        g_cBh[nidx*HD+tid] = bb;
    } else {
        int idx = (blockIdx.x - NNODE)*blockDim.x + threadIdx.x;
        if (idx >= NB*NV*HD) return;
        int k = idx % HD;
        int j = (idx / HD) % NV;
        int b = idx / (HD*NV);
        int lab = labv[b*NV+j];
        int pos = posv[b*NV+j];
        int aa  = pept[b*15 + pos - 1];
        const float* W = W1 + l*161*HD;
        g_cBv[idx] = W[(FD+lab)*HD+k] + W[(FD+44+aa)*HD+k] + W[(FD+64+pos-1)*HD+k];
    }
}

// smem float layout
#define OFF_W2    0
#define OFF_WC1   16384
#define OFF_B2    32768
#define OFF_BC1   (OFF_B2 + HD)
#define OFF_WC2   (OFF_BC1 + HD)
#define OFF_W1D   (OFF_WC2 + HD)
#define OFF_W1B   (OFF_W1D + HD)
#define OFF_CA    (OFF_W1B + HD)
#define OFF_M1    (OFF_CA + HD)
#define OFF_M2    (OFF_M1 + ETILE*132)
#define OFF_AGGM  (OFF_M2 + ETILE*132)
#define OFF_AGGP  (OFF_AGGM + HD)
#define OFF_CWP   (OFF_AGGP + 4*HD)
#define OFF_DIFF  (OFF_CWP + ETILE*4)
#define OFF_DIST  (OFF_DIFF + ETILE*3)
#define OFF_BOND  (OFF_DIST + ETILE)
#define OFF_EMS   (OFF_BOND + ETILE)
#define OFF_CWS   (OFF_EMS + ETILE)
#define OFF_XR    (OFF_CWS + ETILE)
#define OFF_AGGX  (OFF_XR + 4)
#define OFF_COLS  (OFF_AGGX + 4)
#define EDGE_SMEM_FLOATS (OFF_COLS + ETILE)
#define EDGE_SMEM_BYTES (EDGE_SMEM_FLOATS*4)

// ------------- edge kernel: 1 block per (b,s,row), 512 threads, tf32 mma -------------
__global__ void __launch_bounds__(ETHREADS, 1)
edge_k(int l,
       const float* __restrict__ W1,
       const float* __restrict__ b2g, const float* __restrict__ bc1g,
       const float* __restrict__ Wc2g,
       const float* __restrict__ x_hv, const float* __restrict__ bondm,
       const float* __restrict__ emhv) {
    extern __shared__ float es[];
    float* W2s   = es + OFF_W2;
    float* Wc1s  = es + OFF_WC1;
    float* b2s   = es + OFF_B2;
    float* bc1s  = es + OFF_BC1;
    float* wc2s  = es + OFF_WC2;
    float* w1d   = es + OFF_W1D;
    float* w1b   = es + OFF_W1B;
    float* cAs   = es + OFF_CA;
    float* m1s   = es + OFF_M1;
    float* m2s   = es + OFF_M2;
    float* aggm  = es + OFF_AGGM;
    float* aggp  = es + OFF_AGGP;
    float* cwp   = es + OFF_CWP;
    float* diffs = es + OFF_DIFF;
    float* dists = es + OFF_DIST;
    float* bonds = es + OFF_BOND;
    float* ems   = es + OFF_EMS;
    float* cws   = es + OFF_CWS;
    float* xrs   = es + OFF_XR;
    float* aggx  = es + OFF_AGGX;
    int*   colss = (int*)(es + OFF_COLS);

    int tid = threadIdx.x;
    int blk = blockIdx.x;
    int r = blk % NHY;
    int s = (blk / NHY) % NS;
    int b = blk / (NHY*NS);
    int nidx = (b*NS+s)*NHY + r;

    // weights: copy pre-permuted tf32 fragments (coalesced, L2-hot)
    const float* W2p  = g_W2p  + l*HD*HD;
    const float* Wc1p = g_Wc1p + l*HD*HD;
    for (int i = tid; i < HD*HD/4; i += ETHREADS) {
        ((float4*)W2s)[i]  = ((const float4*)W2p)[i];
        ((float4*)Wc1s)[i] = ((const float4*)Wc1p)[i];
    }
    if (tid < HD) {
        b2s [tid] = b2g [l*HD+tid];
        bc1s[tid] = bc1g[l*HD+tid];
        wc2s[tid] = Wc2g[l*HD+tid];
        w1d [tid] = W1[(l*161+158)*HD+tid];
        w1b [tid] = W1[(l*161+159)*HD+tid];
        cAs [tid] = g_cA[nidx*HD+tid];
        aggm[tid] = 0.f;
    }
    if (tid < 3) { xrs[tid] = g_x[nidx*3+tid]; aggx[tid] = 0.f; }
    int hh0   = g_start[b*(NHY+1)+r];
    int hhcnt = g_start[b*(NHY+1)+r+1] - hh0;
    int ne = NV + hhcnt;
    int ntile = (ne + ETILE - 1) / ETILE;
    __syncthreads();

    int lane = tid & 31;
    int warp = tid >> 5;
    int wm = warp & 3, wn = warp >> 2;
    int e0w = wm*16;
    int g = lane >> 2, t4 = lane & 3;
    int eA = e0w + g, eB = e0w + g + 8;
    int nb = wn*32;
    const uint2* W2w  = (const uint2*)W2s;
    const uint2* Wc1w = (const uint2*)Wc1s;

    for (int tile = 0; tile < ntile; ++tile) {
        // --- stage 0: per-edge scalars ---
        if (tid < ETILE) {
            int e = tile*ETILE + tid;
            int col = 0; float bond = 0.f, em = 0.f;
            float d0 = 0.f, d1 = 0.f, d2 = 0.f;
            if (e < NV) {
                col  = NHY + e;
                bond = bondm[(b*NHY+r)*NV + e];
                em   = emhv [(b*NHY+r)*NV + e];
            } else if (e < ne) {
                int ii = hh0 + (e - NV);
                col = g_col[b*NE+ii];
                em  = g_em [b*NE+ii];
            }
            if (e < ne) {
                const float* xc = (col >= NHY) ? (x_hv + (b*NV + (col-NHY))*3)
                                               : (g_x + ((b*NS+s)*NHY+col)*3);
                d0 = xrs[0]-xc[0]; d1 = xrs[1]-xc[1]; d2 = xrs[2]-xc[2];
            }
            diffs[tid*3+0]=d0; diffs[tid*3+1]=d1; diffs[tid*3+2]=d2;
            dists[tid] = sqrtf(d0*d0 + d1*d1 + d2*d2);
            bonds[tid] = bond; ems[tid] = em; colss[tid] = col;
        }
        __syncthreads();
        // --- stage 1: m1 = silu(cA + cB[col] + d*wd + bond*wb), tf32-rounded ---
        #pragma unroll
        for (int rep = 0; rep < 4; ++rep) {
            int q = rep*ETHREADS + tid;
            int e = q >> 5;
            int k4 = (q & 31) << 2;
            int col = colss[e];
            const float* cb = (col >= NHY) ? (g_cBv + (b*NV + (col-NHY))*HD)
                                           : (g_cBh + (((b*NS+s)*NHY)+col)*HD);
            float4 cv = *(const float4*)(cb + k4);
            float dd = dists[e], bo = bonds[e];
            float4 o;
            o.x = tf32f(silu_f(cAs[k4+0] + cv.x + dd*w1d[k4+0] + bo*w1b[k4+0]));
            o.y = tf32f(silu_f(cAs[k4+1] + cv.y + dd*w1d[k4+1] + bo*w1b[k4+1]));
            o.z = tf32f(silu_f(cAs[k4+2] + cv.z + dd*w1d[k4+2] + bo*w1b[k4+2]));
            o.w = tf32f(silu_f(cAs[k4+3] + cv.w + dd*w1d[k4+3] + bo*w1b[k4+3]));
            *(float4*)(m1s + e*132 + k4) = o;
        }
        __syncthreads();
        // --- stage 2: m2 = silu(m1@W2 + b2) * emask  (tf32 mma) ---
        {
            float acc[4][4];
            #pragma unroll
            for (int n = 0; n < 4; ++n) {
                float2 bb = *(const float2*)(b2s + nb + n*8 + 2*t4);
                acc[n][0]=bb.x; acc[n][1]=bb.y; acc[n][2]=bb.x; acc[n][3]=bb.y;
            }
            const uint32_t* rA = (const uint32_t*)m1s + eA*132;
            const uint32_t* rB = (const uint32_t*)m1s + eB*132;
            #pragma unroll
            for (int kt = 0; kt < 16; ++kt) {
                uint32_t a0 = rA[kt*8+t4], a1 = rB[kt*8+t4];
                uint32_t a2 = rA[kt*8+t4+4], a3 = rB[kt*8+t4+4];
                #pragma unroll
                for (int n = 0; n < 4; ++n) {
                    uint2 bv = W2w[(kt*16 + wn*4 + n)*32 + lane];
                    mma_tf32(acc[n], a0, a1, a2, a3, bv.x, bv.y);
                }
            }
            float emA = ems[eA], emB = ems[eB];
            #pragma unroll
            for (int n = 0; n < 4; ++n) {
                float f0 = silu_f(acc[n][0])*emA, f1 = silu_f(acc[n][1])*emA;
                float f2 = silu_f(acc[n][2])*emB, f3 = silu_f(acc[n][3])*emB;
                *(float2*)(m2s + eA*132 + nb + n*8 + 2*t4) = make_float2(tf32f(f0), tf32f(f1));
                *(float2*)(m2s + eB*132 + nb + n*8 + 2*t4) = make_float2(tf32f(f2), tf32f(f3));
            }
        }
        __syncthreads();
        // --- stage 3: cw = silu(m2@Wc1 + bc1) . Wc2  (tf32 mma + shfl reduce) ---
        {
            float acc[4][4];
            #pragma unroll
            for (int n = 0; n < 4; ++n) {
                float2 bb = *(const float2*)(bc1s + nb + n*8 + 2*t4);
                acc[n][0]=bb.x; acc[n][1]=bb.y; acc[n][2]=bb.x; acc[n][3]=bb.y;
            }
            const uint32_t* rA = (const uint32_t*)m2s + eA*132;
            const uint32_t* rB = (const uint32_t*)m2s + eB*132;
            #pragma unroll
            for (int kt = 0; kt < 16; ++kt) {
                uint32_t a0 = rA[kt*8+t4], a1 = rB[kt*8+t4];
                uint32_t a2 = rA[kt*8+t4+4], a3 = rB[kt*8+t4+4];
                #pragma unroll
                for (int n = 0; n < 4; ++n) {
                    uint2 bv = Wc1w[(kt*16 + wn*4 + n)*32 + lane];
                    mma_tf32(acc[n], a0, a1, a2, a3, bv.x, bv.y);
                }
            }
            float pA = 0.f, pB = 0.f;
            #pragma unroll
            for (int n = 0; n < 4; ++n) {
                float2 w = *(const float2*)(wc2s + nb + n*8 + 2*t4);
                pA += silu_f(acc[n][0])*w.x + silu_f(acc[n][1])*w.y;
                pB += silu_f(acc[n][2])*w.x + silu_f(acc[n][3])*w.y;
            }
            pA += __shfl_xor_sync(0xffffffffu, pA, 1);
            pA += __shfl_xor_sync(0xffffffffu, pA, 2);
            pB += __shfl_xor_sync(0xffffffffu, pB, 1);
            pB += __shfl_xor_sync(0xffffffffu, pB, 2);
            if (t4 == 0) {
                cwp[eA*4 + wn] = pA;
                cwp[eB*4 + wn] = pB;
            }
        }
        __syncthreads();
        // --- stage 4a: partial m2 aggregation (4 groups of 16 edges) ---
        {
            int gg = tid >> 7;
            int colx = tid & 127;
            float a = 0.f;
            #pragma unroll
            for (int i = 0; i < 16; ++i) a += m2s[(gg*16+i)*132 + colx];
            aggp[gg*HD + colx] = a;
        }
        __syncthreads();
        // --- stage 4b: combine partials; reduce cw ---
        if (tid < HD) {
            aggm[tid] += aggp[tid] + aggp[HD+tid] + aggp[2*HD+tid] + aggp[3*HD+tid];
        } else if (tid < HD + ETILE) {
            int e = tid - HD;
            cws[e] = cwp[e*4] + cwp[e*4+1] + cwp[e*4+2] + cwp[e*4+3];
        }
        __syncthreads();
        // --- stage 4c: aggregate diff*cw ---
        if (tid < 3) {
            float a = aggx[tid];
            #pragma unroll
            for (int e = 0; e < ETILE; ++e) a += diffs[e*3+tid]*cws[e];
            aggx[tid] = a;
        }
        __syncthreads();
    }
    if (tid < HD) g_aggm[nidx*HD+tid] = aggm[tid];
    if (tid < 3)  g_aggx[nidx*3+tid]  = aggx[tid];
}

// ------------- node update -------------
__global__ void node_k(int l, const float* __restrict__ Wn1, const float* __restrict__ bn1,
                       const float* __restrict__ Wn2, const float* __restrict__ bn2) {
    __shared__ float ins[WN1R+1];
    __shared__ float hid[HD];
    int nidx = blockIdx.x;
    int tid = threadIdx.x;
    if (tid < FD) ins[tid] = g_feat[nidx*FD+tid];
    ins[FD+tid] = g_aggm[nidx*HD+tid];
    __syncthreads();
    const float* W = Wn1 + l*WN1R*HD;
    float h = bn1[l*HD+tid];
    #pragma unroll 4
    for (int i = 0; i < WN1R; ++i) h = fmaf(ins[i], W[i*HD+tid], h);
    hid[tid] = silu_f(h);
    __syncthreads();
    if (tid < FD) {
        const float* V = Wn2 + l*HD*FD;
        float o = bn2[l*FD+tid];
        #pragma unroll 4
        for (int k = 0; k < HD; ++k) o = fmaf(hid[k], V[k*FD+tid], o);
        g_feat[nidx*FD+tid] += o;
    }
    if (tid < 3) g_x[nidx*3+tid] += g_aggx[nidx*3+tid];
}

// ------------- output -------------
__global__ void final_k(const float* __restrict__ x_h, const float* __restrict__ x_hv,
                        const int* __restrict__ bound, const float* __restrict__ mask,
                        float* __restrict__ out) {
    int idx = blockIdx.x*blockDim.x + threadIdx.x;
    if (idx >= NNODE*3) return;
    int c = idx % 3;
    int n = idx / 3;
    int r = n % NHY;
    int b = n / (NHY*NS);
    int ba = bound[b*NHY+r];
    float x0 = x_h[idx] + x_hv[(b*NV+ba)*3+c];
    out[idx] = (g_x[idx] - x0) * mask[b*NHY+r];
}

extern "C" void kernel_launch(void* const* d_in, const int* in_sizes, int n_in,
                              void* d_out, int out_size) {
    const float* t     = (const float*)d_in[0];
    const float* x_h   = (const float*)d_in[1];
    const float* x_hv  = (const float*)d_in[2];
    const float* bondm = (const float*)d_in[3];
    const float* emhv  = (const float*)d_in[4];
    const float* emhh  = (const float*)d_in[5];
    const float* amask = (const float*)d_in[6];
    const float* W1    = (const float*)d_in[7];
    const float* b1    = (const float*)d_in[8];
    const float* W2    = (const float*)d_in[9];
    const float* b2    = (const float*)d_in[10];
    const float* Wc1   = (const float*)d_in[11];
    const float* bc1   = (const float*)d_in[12];
    const float* Wc2   = (const float*)d_in[13];
    const float* Wn1   = (const float*)d_in[14];
    const float* bn1   = (const float*)d_in[15];
    const float* Wn2   = (const float*)d_in[16];
    const float* bn2   = (const float*)d_in[17];
    const int* pept    = (const int*)d_in[18];
    const int* labv    = (const int*)d_in[19];
    const int* labh    = (const int*)d_in[20];
    const int* posv    = (const int*)d_in[21];
    const int* posh    = (const int*)d_in[22];
    const int* edges   = (const int*)d_in[23];
    const int* bound   = (const int*)d_in[24];
    float* out = (float*)d_out;

    cudaFuncSetAttribute(edge_k, cudaFuncAttributeMaxDynamicSharedMemorySize, EDGE_SMEM_BYTES);

    // launch order keeps the ncu window (-s 5 -c 1) on edge_k:
    // prep(0), wperm(1), nodecb(2), edge(3) <- captured
    prep_k<<<NB + (NNODE+127)/128, 128>>>(edges, emhh, x_h, x_hv, bound, labh, posh, pept);
    wperm_k<<<(4*HD*HD+255)/256, 256>>>(W2, Wc1);
    for (int l = 0; l < NL; ++l) {
        nodecb_k<<<NNODE + (NB*NV*HD+127)/128, HD>>>(l, W1, b1, t, labv, posv, pept);
        edge_k<<<NNODE, ETHREADS, EDGE_SMEM_BYTES>>>(l, W1, b2, bc1, Wc2,
                                                     x_hv, bondm, emhv);
        node_k<<<NNODE, HD>>>(l, Wn1, bn1, Wn2, bn2);
    }
    final_k<<<(NNODE*3+127)/128, 128>>>(x_h, x_hv, bound, amask, out);
}

// round 9
// speedup vs baseline: 4.8622x; 1.6620x over previous
#include <cuda_runtime.h>
#include <cstdint>

#define NB 8
#define NS 4
#define NHY 50
#define NV 200
#define NE 400
#define NL 2
#define FD 79
#define HD 128
#define WN1R 207
#define NNODE (NB*NS*NHY)

#define ETILE 32
#define ETHREADS 256

// ------------- device scratch (no allocation) -------------
__device__ float g_cA [NNODE*HD];
__device__ float g_cBh[NNODE*HD];
__device__ float g_cBv[NB*NV*HD];
__device__ float g_feat[NNODE*FD];
__device__ float g_x   [NNODE*3];
__device__ float g_aggm[NNODE*HD];
__device__ float g_aggx[NNODE*3];
__device__ int   g_start[NB*(NHY+1)];
__device__ int   g_col[NB*NE];
__device__ float g_em [NB*NE];
__device__ uint32_t g_W2p [NL*8192];   // W2 bf16x2, mma fragment order
__device__ uint32_t g_Wc1p[NL*8192];   // Wc1 bf16x2, mma fragment order

__device__ __forceinline__ float silu_f(float x) {
    return __fdividef(x, 1.0f + __expf(-x));
}
// pack two fp32 -> bf16x2 (lo = first arg, hi = second arg)
__device__ __forceinline__ uint32_t bf2(float lo, float hi) {
    uint32_t r;
    asm("cvt.rn.bf16x2.f32 %0, %1, %2;" : "=r"(r) : "f"(hi), "f"(lo));
    return r;
}
__device__ __forceinline__ void mma_bf16(float acc[4],
                                         uint32_t a0, uint32_t a1, uint32_t a2, uint32_t a3,
                                         uint32_t b0, uint32_t b1) {
    asm("mma.sync.aligned.m16n8k16.row.col.f32.bf16.bf16.f32 "
        "{%0,%1,%2,%3},{%4,%5,%6,%7},{%8,%9},{%0,%1,%2,%3};"
        : "+f"(acc[0]), "+f"(acc[1]), "+f"(acc[2]), "+f"(acc[3])
        : "r"(a0), "r"(a1), "r"(a2), "r"(a3), "r"(b0), "r"(b1));
}

// ------------- merged prolog: blocks [0,NB) build CSR, rest do node init -------------
__global__ void prep_k(const int* __restrict__ e, const float* __restrict__ em,
                       const float* __restrict__ x_h, const float* __restrict__ x_hv,
                       const int* __restrict__ bound, const int* __restrict__ labh,
                       const int* __restrict__ posh, const int* __restrict__ pept) {
    __shared__ int cnt[NHY+1];
    if (blockIdx.x < NB) {
        int b = blockIdx.x, t = threadIdx.x;
        if (t <= NHY) cnt[t] = 0;
        __syncthreads();
        if (t < NHY) {
            int c = 0;
            for (int i = 0; i < NE; i++) if (e[(b*NE+i)*2] == t) c++;
            cnt[t+1] = c;
        }
        __syncthreads();
        if (t == 0) for (int i = 0; i < NHY; i++) cnt[i+1] += cnt[i];
        __syncthreads();
        if (t <= NHY) g_start[b*(NHY+1)+t] = cnt[t];
        if (t < NHY) {
            int p = cnt[t];
            for (int i = 0; i < NE; i++) if (e[(b*NE+i)*2] == t) {
                g_col[b*NE+p] = e[(b*NE+i)*2+1];
                g_em [b*NE+p] = em[b*NE+i];
                p++;
            }
        }
    } else {
        int idx = (blockIdx.x - NB)*blockDim.x + threadIdx.x;
        if (idx >= NNODE) return;
        int r = idx % NHY;
        int b = idx / (NHY*NS);
        int ba = bound[b*NHY+r];
        for (int c = 0; c < 3; ++c)
            g_x[idx*3+c] = x_h[idx*3+c] + x_hv[(b*NV+ba)*3+c];
        int lab = labh[b*NHY+r], pos = posh[b*NHY+r];
        int aa = pept[b*15 + pos - 1];
        float* f = g_feat + idx*FD;
        for (int i = 0; i < FD; ++i) f[i] = 0.f;
        f[lab] = 1.f; f[44+aa] = 1.f; f[64+pos-1] = 1.f;
    }
}

// ------------- weight permute into bf16 m16n8k16 B-fragment order -------------
// dst[(kt*16+nt)*64 + lane*2 + r] = pack(W[k0][n], W[k0+1][n]),
//   k0 = kt*16 + (lane&3)*2 + 8r, n = nt*8 + (lane>>2)
__global__ void wperm_k(const float* __restrict__ W2, const float* __restrict__ Wc1) {
    int idx = blockIdx.x*blockDim.x + threadIdx.x;   // 0 .. 4*8192-1
    if (idx >= 4*8192) return;
    int m = idx >> 13;          // layer = m>>1, which = m&1
    int j = idx & 8191;
    int kt = j >> 10;
    int rest = j & 1023;
    int nt = rest >> 6;
    int q = rest & 63;
    int lane = q >> 1, r = q & 1;
    int k0 = kt*16 + (lane & 3)*2 + 8*r;
    int n  = nt*8 + (lane >> 2);
    int l = m >> 1;
    const float* src = (m & 1) ? Wc1 : W2;
    float lo = src[(l*HD + k0)*HD + n];
    float hi = src[(l*HD + k0 + 1)*HD + n];
    uint32_t* dst = (m & 1) ? g_Wc1p : g_W2p;
    dst[l*8192 + j] = bf2(lo, hi);
}

// ------------- per layer merged: blocks [0,NNODE) h-node cA/cB, rest heavy cB -------------
__global__ void nodecb_k(int l, const float* __restrict__ W1,
                         const float* __restrict__ b1, const float* __restrict__ t,
                         const int* __restrict__ labv, const int* __restrict__ posv,
                         const int* __restrict__ pept) {
    __shared__ float fs[FD];
    if (blockIdx.x < NNODE) {
        int nidx = blockIdx.x;
        int b = nidx / (NHY*NS);
        int tid = threadIdx.x;
        if (tid < FD) fs[tid] = g_feat[nidx*FD+tid];
        __syncthreads();
        const float* W = W1 + l*161*HD;
        float a  = b1[l*HD+tid] + t[b]*W[160*HD+tid];
        float bb = 0.f;
        #pragma unroll 4
        for (int f = 0; f < FD; ++f) {
            float fv = fs[f];
            a  = fmaf(fv, W[f*HD+tid], a);
            bb = fmaf(fv, W[(FD+f)*HD+tid], bb);
        }
        g_cA [nidx*HD+tid] = a;
        g_cBh[nidx*HD+tid] = bb;
    } else {
        int idx = (blockIdx.x - NNODE)*blockDim.x + threadIdx.x;
        if (idx >= NB*NV*HD) return;
        int k = idx % HD;
        int j = (idx / HD) % NV;
        int b = idx / (HD*NV);
        int lab = labv[b*NV+j];
        int pos = posv[b*NV+j];
        int aa  = pept[b*15 + pos - 1];
        const float* W = W1 + l*161*HD;
        g_cBv[idx] = W[(FD+lab)*HD+k] + W[(FD+44+aa)*HD+k] + W[(FD+64+pos-1)*HD+k];
    }
}

// smem layout in 4-byte words
#define W_W2    0                    // 8192 (bf16x2)
#define W_WC1   8192                 // 8192
#define W_M1    16384                // 32*68 = 2176 (bf16x2, row stride 68 words)
#define W_M2    18560                // 2176
#define W_B2    20736                // 128 fp32
#define W_BC1   20864
#define W_WC2   20992
#define W_W1D   21120
#define W_W1B   21248
#define W_CA    21376
#define W_AGGM  21504                // 128
#define W_AGGP  21632                // 512 (4 groups x 128)
#define W_CWP   22144                // 128 (32 edges x 4)
#define W_DIFF  22272                // 96
#define W_DIST  22368                // 32
#define W_BOND  22400                // 32
#define W_EMS   22432                // 32
#define W_CWS   22464                // 32
#define W_XR    22496                // 4
#define W_AGGX  22500                // 4
#define W_COLS  22504                // 32
#define EDGE_SMEM_WORDS 22536
#define EDGE_SMEM_BYTES (EDGE_SMEM_WORDS*4)

// ------------- edge kernel: 1 block per (b,s,row), 256 threads, 2 blocks/SM -------------
__global__ void __launch_bounds__(ETHREADS, 2)
edge_k(int l,
       const float* __restrict__ W1,
       const float* __restrict__ b2g, const float* __restrict__ bc1g,
       const float* __restrict__ Wc2g,
       const float* __restrict__ x_hv, const float* __restrict__ bondm,
       const float* __restrict__ emhv) {
    extern __shared__ float es[];
    uint32_t* W2w  = (uint32_t*)(es + W_W2);
    uint32_t* Wc1w = (uint32_t*)(es + W_WC1);
    uint32_t* m1w  = (uint32_t*)(es + W_M1);
    uint32_t* m2w  = (uint32_t*)(es + W_M2);
    float* b2s   = es + W_B2;
    float* bc1s  = es + W_BC1;
    float* wc2s  = es + W_WC2;
    float* w1d   = es + W_W1D;
    float* w1b   = es + W_W1B;
    float* cAs   = es + W_CA;
    float* aggm  = es + W_AGGM;
    float* aggp  = es + W_AGGP;
    float* cwp   = es + W_CWP;
    float* diffs = es + W_DIFF;
    float* dists = es + W_DIST;
    float* bonds = es + W_BOND;
    float* ems   = es + W_EMS;
    float* cws   = es + W_CWS;
    float* xrs   = es + W_XR;
    float* aggx  = es + W_AGGX;
    int*   colss = (int*)(es + W_COLS);

    int tid = threadIdx.x;
    int blk = blockIdx.x;
    int r = blk % NHY;
    int s = (blk / NHY) % NS;
    int b = blk / (NHY*NS);
    int nidx = (b*NS+s)*NHY + r;

    // copy pre-permuted bf16 weights (8192 words each = 2048 uint4)
    {
        const uint4* src2 = (const uint4*)(g_W2p  + l*8192);
        const uint4* srcc = (const uint4*)(g_Wc1p + l*8192);
        uint4* d2 = (uint4*)W2w;
        uint4* dc = (uint4*)Wc1w;
        for (int i = tid; i < 2048; i += ETHREADS) {
            d2[i] = src2[i];
            dc[i] = srcc[i];
        }
    }
    if (tid < HD) {
        b2s [tid] = b2g [l*HD+tid];
        bc1s[tid] = bc1g[l*HD+tid];
        wc2s[tid] = Wc2g[l*HD+tid];
        w1d [tid] = W1[(l*161+158)*HD+tid];
        w1b [tid] = W1[(l*161+159)*HD+tid];
        cAs [tid] = g_cA[nidx*HD+tid];
        aggm[tid] = 0.f;
    }
    if (tid < 3) { xrs[tid] = g_x[nidx*3+tid]; aggx[tid] = 0.f; }
    int hh0   = g_start[b*(NHY+1)+r];
    int hhcnt = g_start[b*(NHY+1)+r+1] - hh0;
    int ne = NV + hhcnt;
    int ntile = (ne + ETILE - 1) / ETILE;
    __syncthreads();

    int lane = tid & 31;
    int warp = tid >> 5;          // 0..7
    int wm = warp & 1, wn = warp >> 1;   // wm: edge half, wn: 32-col group
    int g = lane >> 2, t4 = lane & 3;
    int eA = wm*16 + g, eB = eA + 8;
    int nb = wn*32;

    for (int tile = 0; tile < ntile; ++tile) {
        // --- stage 0: per-edge scalars ---
        if (tid < ETILE) {
            int e = tile*ETILE + tid;
            int col = 0; float bond = 0.f, em = 0.f;
            float d0 = 0.f, d1 = 0.f, d2 = 0.f;
            if (e < NV) {
                col  = NHY + e;
                bond = bondm[(b*NHY+r)*NV + e];
                em   = emhv [(b*NHY+r)*NV + e];
            } else if (e < ne) {
                int ii = hh0 + (e - NV);
                col = g_col[b*NE+ii];
                em  = g_em [b*NE+ii];
            }
            if (e < ne) {
                const float* xc = (col >= NHY) ? (x_hv + (b*NV + (col-NHY))*3)
                                               : (g_x + ((b*NS+s)*NHY+col)*3);
                d0 = xrs[0]-xc[0]; d1 = xrs[1]-xc[1]; d2 = xrs[2]-xc[2];
            }
            diffs[tid*3+0]=d0; diffs[tid*3+1]=d1; diffs[tid*3+2]=d2;
            dists[tid] = sqrtf(d0*d0 + d1*d1 + d2*d2);
            bonds[tid] = bond; ems[tid] = em; colss[tid] = col;
        }
        __syncthreads();
        // --- stage 1: m1 = silu(cA + cB[col] + d*wd + bond*wb) -> bf16x2 ---
        #pragma unroll
        for (int rep = 0; rep < 4; ++rep) {
            int q = rep*ETHREADS + tid;
            int e = q >> 5;
            int k4 = (q & 31) << 2;
            int col = colss[e];
            const float* cb = (col >= NHY) ? (g_cBv + (b*NV + (col-NHY))*HD)
                                           : (g_cBh + (((b*NS+s)*NHY)+col)*HD);
            float4 cv = *(const float4*)(cb + k4);
            float dd = dists[e], bo = bonds[e];
            float o0 = silu_f(cAs[k4+0] + cv.x + dd*w1d[k4+0] + bo*w1b[k4+0]);
            float o1 = silu_f(cAs[k4+1] + cv.y + dd*w1d[k4+1] + bo*w1b[k4+1]);
            float o2 = silu_f(cAs[k4+2] + cv.z + dd*w1d[k4+2] + bo*w1b[k4+2]);
            float o3 = silu_f(cAs[k4+3] + cv.w + dd*w1d[k4+3] + bo*w1b[k4+3]);
            uint2 pk = make_uint2(bf2(o0, o1), bf2(o2, o3));
            *(uint2*)(m1w + e*68 + (k4 >> 1)) = pk;
        }
        __syncthreads();
        // --- stage 2: m2 = silu(m1@W2 + b2) * emask  (bf16 mma k16) ---
        {
            float acc[4][4];
            #pragma unroll
            for (int n = 0; n < 4; ++n) {
                float2 bb = *(const float2*)(b2s + nb + n*8 + 2*t4);
                acc[n][0]=bb.x; acc[n][1]=bb.y; acc[n][2]=bb.x; acc[n][3]=bb.y;
            }
            #pragma unroll
            for (int kt = 0; kt < 8; ++kt) {
                uint32_t a0 = m1w[eA*68 + kt*8 + t4];
                uint32_t a1 = m1w[eB*68 + kt*8 + t4];
                uint32_t a2 = m1w[eA*68 + kt*8 + t4 + 4];
                uint32_t a3 = m1w[eB*68 + kt*8 + t4 + 4];
                #pragma unroll
                for (int n = 0; n < 4; ++n) {
                    uint2 bv = *(const uint2*)(W2w + (kt*16 + wn*4 + n)*64 + lane*2);
                    mma_bf16(acc[n], a0, a1, a2, a3, bv.x, bv.y);
                }
            }
            float emA = ems[eA], emB = ems[eB];
            #pragma unroll
            for (int n = 0; n < 4; ++n) {
                int c2 = nb/2 + n*4 + t4;   // b32 index of col pair
                m2w[eA*68 + c2] = bf2(silu_f(acc[n][0])*emA, silu_f(acc[n][1])*emA);
                m2w[eB*68 + c2] = bf2(silu_f(acc[n][2])*emB, silu_f(acc[n][3])*emB);
            }
        }
        __syncthreads();
        // --- stage 3: cw = silu(m2@Wc1 + bc1) . Wc2  (bf16 mma + shfl reduce) ---
        {
            float acc[4][4];
            #pragma unroll
            for (int n = 0; n < 4; ++n) {
                float2 bb = *(const float2*)(bc1s + nb + n*8 + 2*t4);
                acc[n][0]=bb.x; acc[n][1]=bb.y; acc[n][2]=bb.x; acc[n][3]=bb.y;
            }
            #pragma unroll
            for (int kt = 0; kt < 8; ++kt) {
                uint32_t a0 = m2w[eA*68 + kt*8 + t4];
                uint32_t a1 = m2w[eB*68 + kt*8 + t4];
                uint32_t a2 = m2w[eA*68 + kt*8 + t4 + 4];
                uint32_t a3 = m2w[eB*68 + kt*8 + t4 + 4];
                #pragma unroll
                for (int n = 0; n < 4; ++n) {
                    uint2 bv = *(const uint2*)(Wc1w + (kt*16 + wn*4 + n)*64 + lane*2);
                    mma_bf16(acc[n], a0, a1, a2, a3, bv.x, bv.y);
                }
            }
            float pA = 0.f, pB = 0.f;
            #pragma unroll
            for (int n = 0; n < 4; ++n) {
                float2 w = *(const float2*)(wc2s + nb + n*8 + 2*t4);
                pA += silu_f(acc[n][0])*w.x + silu_f(acc[n][1])*w.y;
                pB += silu_f(acc[n][2])*w.x + silu_f(acc[n][3])*w.y;
            }
            pA += __shfl_xor_sync(0xffffffffu, pA, 1);
            pA += __shfl_xor_sync(0xffffffffu, pA, 2);
            pB += __shfl_xor_sync(0xffffffffu, pB, 1);
            pB += __shfl_xor_sync(0xffffffffu, pB, 2);
            if (t4 == 0) {
                cwp[eA*4 + wn] = pA;
                cwp[eB*4 + wn] = pB;
            }
        }
        __syncthreads();
        // --- stage 4a: partial m2 aggregation (4 groups of 8 edges, col pairs) ---
        {
            int gg = tid >> 6;            // 0..3
            int cp = tid & 63;            // col pair 0..63
            float alo = 0.f, ahi = 0.f;
            #pragma unroll
            for (int i = 0; i < 8; ++i) {
                uint32_t u = m2w[(gg*8+i)*68 + cp];
                alo += __uint_as_float(u << 16);
                ahi += __uint_as_float(u & 0xFFFF0000u);
            }
            aggp[gg*HD + cp*2]     = alo;
            aggp[gg*HD + cp*2 + 1] = ahi;
        }
        __syncthreads();
        // --- stage 4b: combine partials; reduce cw ---
        if (tid < HD) {
            aggm[tid] += aggp[tid] + aggp[HD+tid] + aggp[2*HD+tid] + aggp[3*HD+tid];
        } else if (tid < HD + ETILE) {
            int e = tid - HD;
            cws[e] = cwp[e*4] + cwp[e*4+1] + cwp[e*4+2] + cwp[e*4+3];
        }
        __syncthreads();
        // --- stage 4c: aggregate diff*cw ---
        if (tid < 3) {
            float a = aggx[tid];
            #pragma unroll
            for (int e = 0; e < ETILE; ++e) a += diffs[e*3+tid]*cws[e];
            aggx[tid] = a;
        }
        __syncthreads();
    }
    if (tid < HD) g_aggm[nidx*HD+tid] = aggm[tid];
    if (tid < 3)  g_aggx[nidx*3+tid]  = aggx[tid];
}

// ------------- node update -------------
__global__ void node_k(int l, const float* __restrict__ Wn1, const float* __restrict__ bn1,
                       const float* __restrict__ Wn2, const float* __restrict__ bn2) {
    __shared__ float ins[WN1R+1];
    __shared__ float hid[HD];
    int nidx = blockIdx.x;
    int tid = threadIdx.x;
    if (tid < FD) ins[tid] = g_feat[nidx*FD+tid];
    ins[FD+tid] = g_aggm[nidx*HD+tid];
    __syncthreads();
    const float* W = Wn1 + l*WN1R*HD;
    float h = bn1[l*HD+tid];
    #pragma unroll 4
    for (int i = 0; i < WN1R; ++i) h = fmaf(ins[i], W[i*HD+tid], h);
    hid[tid] = silu_f(h);
    __syncthreads();
    if (tid < FD) {
        const float* V = Wn2 + l*HD*FD;
        float o = bn2[l*FD+tid];
        #pragma unroll 4
        for (int k = 0; k < HD; ++k) o = fmaf(hid[k], V[k*FD+tid], o);
        g_feat[nidx*FD+tid] += o;
    }
    if (tid < 3) g_x[nidx*3+tid] += g_aggx[nidx*3+tid];
}

// ------------- output -------------
__global__ void final_k(const float* __restrict__ x_h, const float* __restrict__ x_hv,
                        const int* __restrict__ bound, const float* __restrict__ mask,
                        float* __restrict__ out) {
    int idx = blockIdx.x*blockDim.x + threadIdx.x;
    if (idx >= NNODE*3) return;
    int c = idx % 3;
    int n = idx / 3;
    int r = n % NHY;
    int b = n / (NHY*NS);
    int ba = bound[b*NHY+r];
    float x0 = x_h[idx] + x_hv[(b*NV+ba)*3+c];
    out[idx] = (g_x[idx] - x0) * mask[b*NHY+r];
}

extern "C" void kernel_launch(void* const* d_in, const int* in_sizes, int n_in,
                              void* d_out, int out_size) {
    const float* t     = (const float*)d_in[0];
    const float* x_h   = (const float*)d_in[1];
    const float* x_hv  = (const float*)d_in[2];
    const float* bondm = (const float*)d_in[3];
    const float* emhv  = (const float*)d_in[4];
    const float* emhh  = (const float*)d_in[5];
    const float* amask = (const float*)d_in[6];
    const float* W1    = (const float*)d_in[7];
    const float* b1    = (const float*)d_in[8];
    const float* W2    = (const float*)d_in[9];
    const float* b2    = (const float*)d_in[10];
    const float* Wc1   = (const float*)d_in[11];
    const float* bc1   = (const float*)d_in[12];
    const float* Wc2   = (const float*)d_in[13];
    const float* Wn1   = (const float*)d_in[14];
    const float* bn1   = (const float*)d_in[15];
    const float* Wn2   = (const float*)d_in[16];
    const float* bn2   = (const float*)d_in[17];
    const int* pept    = (const int*)d_in[18];
    const int* labv    = (const int*)d_in[19];
    const int* labh    = (const int*)d_in[20];
    const int* posv    = (const int*)d_in[21];
    const int* posh    = (const int*)d_in[22];
    const int* edges   = (const int*)d_in[23];
    const int* bound   = (const int*)d_in[24];
    float* out = (float*)d_out;

    cudaFuncSetAttribute(edge_k, cudaFuncAttributeMaxDynamicSharedMemorySize, EDGE_SMEM_BYTES);

    // launch order keeps the ncu window (-s 5 -c 1) on edge_k:
    // prep(0), wperm(1), nodecb(2), edge(3) <- captured
    prep_k<<<NB + (NNODE+127)/128, 128>>>(edges, emhh, x_h, x_hv, bound, labh, posh, pept);
    wperm_k<<<(4*8192+255)/256, 256>>>(W2, Wc1);
    for (int l = 0; l < NL; ++l) {
        nodecb_k<<<NNODE + (NB*NV*HD+127)/128, HD>>>(l, W1, b1, t, labv, posv, pept);
        edge_k<<<NNODE, ETHREADS, EDGE_SMEM_BYTES>>>(l, W1, b2, bc1, Wc2,
                                                     x_hv, bondm, emhv);
        node_k<<<NNODE, HD>>>(l, Wn1, bn1, Wn2, bn2);
    }
    final_k<<<(NNODE*3+127)/128, 128>>>(x_h, x_hv, bound, amask, out);
}

// round 11
// speedup vs baseline: 5.0985x; 1.0486x over previous
#include <cuda_runtime.h>
#include <cstdint>

#define NB 8
#define NS 4
#define NHY 50
#define NV 200
#define NE 400
#define NL 2
#define FD 79
#define HD 128
#define WN1R 207
#define NNODE (NB*NS*NHY)

#define ETHREADS 256

// ------------- device scratch (no allocation) -------------
__device__ float g_cA [NNODE*HD];
__device__ float g_cBh[NNODE*HD];
__device__ float g_cBv[NB*NV*HD];
__device__ float g_feat[NNODE*FD];
__device__ float g_x   [NNODE*3];
__device__ float g_aggm[NNODE*HD];
__device__ float g_aggx[NNODE*3];
__device__ int   g_start[NB*(NHY+1)];
__device__ int   g_col[NB*NE];
__device__ float g_em [NB*NE];
__device__ uint32_t g_W2p [NL*8192];   // W2 bf16x2, mma fragment order
__device__ uint32_t g_Wc1p[NL*8192];   // Wc1 bf16x2, mma fragment order

__device__ __forceinline__ float silu_f(float x) {
    return __fdividef(x, 1.0f + __expf(-x));
}
__device__ __forceinline__ uint32_t bf2(float lo, float hi) {
    uint32_t r;
    asm("cvt.rn.bf16x2.f32 %0, %1, %2;" : "=r"(r) : "f"(hi), "f"(lo));
    return r;
}
__device__ __forceinline__ void mma_bf16(float acc[4],
                                         uint32_t a0, uint32_t a1, uint32_t a2, uint32_t a3,
                                         uint32_t b0, uint32_t b1) {
    asm("mma.sync.aligned.m16n8k16.row.col.f32.bf16.bf16.f32 "
        "{%0,%1,%2,%3},{%4,%5,%6,%7},{%8,%9},{%0,%1,%2,%3};"
        : "+f"(acc[0]), "+f"(acc[1]), "+f"(acc[2]), "+f"(acc[3])
        : "r"(a0), "r"(a1), "r"(a2), "r"(a3), "r"(b0), "r"(b1));
}
#define PBAR(id) asm volatile("bar.sync %0, 64;" :: "r"(id) : "memory")

// ------------- merged prolog: blocks [0,NB) build CSR, rest do node init -------------
__global__ void prep_k(const int* __restrict__ e, const float* __restrict__ em,
                       const float* __restrict__ x_h, const float* __restrict__ x_hv,
                       const int* __restrict__ bound, const int* __restrict__ labh,
                       const int* __restrict__ posh, const int* __restrict__ pept) {
    __shared__ int cnt[NHY+1];
    if (blockIdx.x < NB) {
        int b = blockIdx.x, t = threadIdx.x;
        if (t <= NHY) cnt[t] = 0;
        __syncthreads();
        if (t < NHY) {
            int c = 0;
            for (int i = 0; i < NE; i++) if (e[(b*NE+i)*2] == t) c++;
            cnt[t+1] = c;
        }
        __syncthreads();
        if (t == 0) for (int i = 0; i < NHY; i++) cnt[i+1] += cnt[i];
        __syncthreads();
        if (t <= NHY) g_start[b*(NHY+1)+t] = cnt[t];
        if (t < NHY) {
            int p = cnt[t];
            for (int i = 0; i < NE; i++) if (e[(b*NE+i)*2] == t) {
                g_col[b*NE+p] = e[(b*NE+i)*2+1];
                g_em [b*NE+p] = em[b*NE+i];
                p++;
            }
        }
    } else {
        int idx = (blockIdx.x - NB)*blockDim.x + threadIdx.x;
        if (idx >= NNODE) return;
        int r = idx % NHY;
        int b = idx / (NHY*NS);
        int ba = bound[b*NHY+r];
        for (int c = 0; c < 3; ++c)
            g_x[idx*3+c] = x_h[idx*3+c] + x_hv[(b*NV+ba)*3+c];
        int lab = labh[b*NHY+r], pos = posh[b*NHY+r];
        int aa = pept[b*15 + pos - 1];
        float* f = g_feat + idx*FD;
        for (int i = 0; i < FD; ++i) f[i] = 0.f;
        f[lab] = 1.f; f[44+aa] = 1.f; f[64+pos-1] = 1.f;
    }
}

// ------------- weight permute into bf16 m16n8k16 B-fragment order -------------
__global__ void wperm_k(const float* __restrict__ W2, const float* __restrict__ Wc1) {
    int idx = blockIdx.x*blockDim.x + threadIdx.x;   // 0 .. 4*8192-1
    if (idx >= 4*8192) return;
    int m = idx >> 13;
    int j = idx & 8191;
    int kt = j >> 10;
    int rest = j & 1023;
    int nt = rest >> 6;
    int q = rest & 63;
    int lane = q >> 1, r = q & 1;
    int k0 = kt*16 + (lane & 3)*2 + 8*r;
    int n  = nt*8 + (lane >> 2);
    int l = m >> 1;
    const float* src = (m & 1) ? Wc1 : W2;
    float lo = src[(l*HD + k0)*HD + n];
    float hi = src[(l*HD + k0 + 1)*HD + n];
    uint32_t* dst = (m & 1) ? g_Wc1p : g_W2p;
    dst[l*8192 + j] = bf2(lo, hi);
}

// ------------- per layer merged: blocks [0,NNODE) h-node cA/cB, rest heavy cB -------------
__global__ void nodecb_k(int l, const float* __restrict__ W1,
                         const float* __restrict__ b1, const float* __restrict__ t,
                         const int* __restrict__ labv, const int* __restrict__ posv,
                         const int* __restrict__ pept) {
    __shared__ float fs[FD];
    if (blockIdx.x < NNODE) {
        int nidx = blockIdx.x;
        int b = nidx / (NHY*NS);
        int tid = threadIdx.x;
        if (tid < FD) fs[tid] = g_feat[nidx*FD+tid];
        __syncthreads();
        const float* W = W1 + l*161*HD;
        float a  = b1[l*HD+tid] + t[b]*W[160*HD+tid];
        float bb = 0.f;
        #pragma unroll 4
        for (int f = 0; f < FD; ++f) {
            float fv = fs[f];
            a  = fmaf(fv, W[f*HD+tid], a);
            bb = fmaf(fv, W[(FD+f)*HD+tid], bb);
        }
        g_cA [nidx*HD+tid] = a;
        g_cBh[nidx*HD+tid] = bb;
    } else {
        int idx = (blockIdx.x - NNODE)*blockDim.x + threadIdx.x;
        if (idx >= NB*NV*HD) return;
        int k = idx % HD;
        int j = (idx / HD) % NV;
        int b = idx / (HD*NV);
        int lab = labv[b*NV+j];
        int pos = posv[b*NV+j];
        int aa  = pept[b*15 + pos - 1];
        const float* W = W1 + l*161*HD;
        g_cBv[idx] = W[(FD+lab)*HD+k] + W[(FD+44+aa)*HD+k] + W[(FD+64+pos-1)*HD+k];
    }
}

// smem layout (4-byte words)
#define W_W2    0        // 8192
#define W_WC1   8192     // 8192
#define W_B2    16384    // 128
#define W_BC1   16512
#define W_WC2   16640
#define W_W1D   16768
#define W_W1B   16896
#define W_CA    17024
#define W_XR    17152    // 4
#define W_PAIR  17160
// per-pair area (stride PSTR):
#define P_M1    0        // 16*68 = 1088 (bf16x2)
#define P_M2    1088     // 1088
#define P_DIST  2176     // 16
#define P_BOND  2192     // 16
#define P_EMS   2208     // 16
#define P_COLS  2224     // 16 (int)
#define P_DIFF  2240     // 48
#define P_CWP   2288     // 32
#define P_AGGM  2320     // 128
#define P_AGGX  2448     // 4
#define PSTR    2456
#define EDGE_SMEM_WORDS (W_PAIR + 4*PSTR)
#define EDGE_SMEM_BYTES (EDGE_SMEM_WORDS*4)

// ------------- edge kernel: 1 block per (b,s,row), 4 independent warp-pairs -------------
__global__ void __launch_bounds__(ETHREADS, 2)
edge_k(int l,
       const float* __restrict__ W1,
       const float* __restrict__ b2g, const float* __restrict__ bc1g,
       const float* __restrict__ Wc2g,
       const float* __restrict__ x_hv, const float* __restrict__ bondm,
       const float* __restrict__ emhv) {
    extern __shared__ float es[];
    uint32_t* W2w  = (uint32_t*)(es + W_W2);
    uint32_t* Wc1w = (uint32_t*)(es + W_WC1);
    float* b2s   = es + W_B2;
    float* bc1s  = es + W_BC1;
    float* wc2s  = es + W_WC2;
    float* w1d   = es + W_W1D;
    float* w1b   = es + W_W1B;
    float* cAs   = es + W_CA;
    float* xrs   = es + W_XR;

    int tid = threadIdx.x;
    int blk = blockIdx.x;
    int r = blk % NHY;
    int s = (blk / NHY) % NS;
    int b = blk / (NHY*NS);
    int nidx = (b*NS+s)*NHY + r;

    int lane = tid & 31;
    int warp = tid >> 5;
    int pair = warp >> 1;
    int wip  = warp & 1;          // warp-in-pair
    int tid64 = (wip << 5) | lane;
    int barid = pair + 1;

    float* ps = es + W_PAIR + pair*PSTR;
    uint32_t* m1P = (uint32_t*)(ps + P_M1);
    uint32_t* m2P = (uint32_t*)(ps + P_M2);
    float* distsP = ps + P_DIST;
    float* bondsP = ps + P_BOND;
    float* emsP   = ps + P_EMS;
    int*   colsP  = (int*)(ps + P_COLS);
    float* diffsP = ps + P_DIFF;
    float* cwpP   = ps + P_CWP;
    float* aggmP  = ps + P_AGGM;
    float* aggxP  = ps + P_AGGX;

    // prolog: weights + small vectors
    {
        const uint4* src2 = (const uint4*)(g_W2p  + l*8192);
        const uint4* srcc = (const uint4*)(g_Wc1p + l*8192);
        uint4* d2 = (uint4*)W2w;
        uint4* dc = (uint4*)Wc1w;
        for (int i = tid; i < 2048; i += ETHREADS) {
            d2[i] = src2[i];
            dc[i] = srcc[i];
        }
    }
    if (tid < HD) {
        b2s [tid] = b2g [l*HD+tid];
        bc1s[tid] = bc1g[l*HD+tid];
        wc2s[tid] = Wc2g[l*HD+tid];
        w1d [tid] = W1[(l*161+158)*HD+tid];
        w1b [tid] = W1[(l*161+159)*HD+tid];
        cAs [tid] = g_cA[nidx*HD+tid];
    }
    if (tid < 3) xrs[tid] = g_x[nidx*3+tid];
    if (tid64 < 4) aggxP[tid64] = 0.f;
    int hh0   = g_start[b*(NHY+1)+r];
    int hhcnt = g_start[b*(NHY+1)+r+1] - hh0;
    int ne = NV + hhcnt;
    __syncthreads();

    int g = lane >> 2, t4 = lane & 3;
    float aggA[8][2];
    #pragma unroll
    for (int n = 0; n < 8; ++n) { aggA[n][0] = 0.f; aggA[n][1] = 0.f; }

    for (int tile = pair; tile*16 < ne; tile += 4) {
        // --- stage 0: per-edge scalars (16 edges) ---
        if (tid64 < 16) {
            int e = tile*16 + tid64;
            int col = 0; float bond = 0.f, em = 0.f;
            float d0 = 0.f, d1 = 0.f, d2 = 0.f;
            if (e < NV) {
                col  = NHY + e;
                bond = bondm[(b*NHY+r)*NV + e];
                em   = emhv [(b*NHY+r)*NV + e];
            } else if (e < ne) {
                int ii = hh0 + (e - NV);
                col = g_col[b*NE+ii];
                em  = g_em [b*NE+ii];
            }
            if (e < ne) {
                const float* xc = (col >= NHY) ? (x_hv + (b*NV + (col-NHY))*3)
                                               : (g_x + ((b*NS+s)*NHY+col)*3);
                d0 = xrs[0]-xc[0]; d1 = xrs[1]-xc[1]; d2 = xrs[2]-xc[2];
            }
            diffsP[tid64*3+0]=d0; diffsP[tid64*3+1]=d1; diffsP[tid64*3+2]=d2;
            distsP[tid64] = sqrtf(d0*d0 + d1*d1 + d2*d2);
            bondsP[tid64] = bond; emsP[tid64] = em; colsP[tid64] = col;
        }
        PBAR(barid);
        // --- stage 1: m1 = silu(cA + cB[col] + d*wd + bond*wb) -> bf16x2 ---
        #pragma unroll
        for (int rep = 0; rep < 8; ++rep) {
            int q = rep*64 + tid64;
            int e = q >> 5;
            int k4 = (q & 31) << 2;
            int col = colsP[e];
            const float* cb = (col >= NHY) ? (g_cBv + (b*NV + (col-NHY))*HD)
                                           : (g_cBh + (((b*NS+s)*NHY)+col)*HD);
            float4 cv = *(const float4*)(cb + k4);
            float dd = distsP[e], bo = bondsP[e];
            float o0 = silu_f(cAs[k4+0] + cv.x + dd*w1d[k4+0] + bo*w1b[k4+0]);
            float o1 = silu_f(cAs[k4+1] + cv.y + dd*w1d[k4+1] + bo*w1b[k4+1]);
            float o2 = silu_f(cAs[k4+2] + cv.z + dd*w1d[k4+2] + bo*w1b[k4+2]);
            float o3 = silu_f(cAs[k4+3] + cv.w + dd*w1d[k4+3] + bo*w1b[k4+3]);
            *(uint2*)(m1P + e*68 + (k4 >> 1)) = make_uint2(bf2(o0, o1), bf2(o2, o3));
        }
        PBAR(barid);
        // --- stage 2: m2 = silu(m1@W2 + b2) * emask; fp32 agg into registers ---
        {
            float acc[8][4];
            #pragma unroll
            for (int n = 0; n < 8; ++n) {
                int cn = (wip*8+n)*8 + 2*t4;
                float2 bb = *(const float2*)(b2s + cn);
                acc[n][0]=bb.x; acc[n][1]=bb.y; acc[n][2]=bb.x; acc[n][3]=bb.y;
            }
            #pragma unroll
            for (int kt = 0; kt < 8; ++kt) {
                uint32_t a0 = m1P[g*68 + kt*8 + t4];
                uint32_t a1 = m1P[(g+8)*68 + kt*8 + t4];
                uint32_t a2 = m1P[g*68 + kt*8 + t4 + 4];
                uint32_t a3 = m1P[(g+8)*68 + kt*8 + t4 + 4];
                #pragma unroll
                for (int n = 0; n < 8; ++n) {
                    uint2 bv = *(const uint2*)(W2w + ((kt*16 + wip*8 + n) << 6) + lane*2);
                    mma_bf16(acc[n], a0, a1, a2, a3, bv.x, bv.y);
                }
            }
            float emA = emsP[g], emB = emsP[g+8];
            #pragma unroll
            for (int n = 0; n < 8; ++n) {
                int c2 = (wip*8+n)*4 + t4;   // b32 col-pair index
                float f0 = silu_f(acc[n][0])*emA, f1 = silu_f(acc[n][1])*emA;
                float f2 = silu_f(acc[n][2])*emB, f3 = silu_f(acc[n][3])*emB;
                m2P[g*68 + c2]     = bf2(f0, f1);
                m2P[(g+8)*68 + c2] = bf2(f2, f3);
                aggA[n][0] += f0 + f2;
                aggA[n][1] += f1 + f3;
            }
        }
        PBAR(barid);
        // --- stage 3: cw = silu(m2@Wc1 + bc1) . Wc2 ---
        {
            float acc[8][4];
            #pragma unroll
            for (int n = 0; n < 8; ++n) {
                int cn = (wip*8+n)*8 + 2*t4;
                float2 bb = *(const float2*)(bc1s + cn);
                acc[n][0]=bb.x; acc[n][1]=bb.y; acc[n][2]=bb.x; acc[n][3]=bb.y;
            }
            #pragma unroll
            for (int kt = 0; kt < 8; ++kt) {
                uint32_t a0 = m2P[g*68 + kt*8 + t4];
                uint32_t a1 = m2P[(g+8)*68 + kt*8 + t4];
                uint32_t a2 = m2P[g*68 + kt*8 + t4 + 4];
                uint32_t a3 = m2P[(g+8)*68 + kt*8 + t4 + 4];
                #pragma unroll
                for (int n = 0; n < 8; ++n) {
                    uint2 bv = *(const uint2*)(Wc1w + ((kt*16 + wip*8 + n) << 6) + lane*2);
                    mma_bf16(acc[n], a0, a1, a2, a3, bv.x, bv.y);
                }
            }
            float pA = 0.f, pB = 0.f;
            #pragma unroll
            for (int n = 0; n < 8; ++n) {
                int cn = (wip*8+n)*8 + 2*t4;
                float2 w = *(const float2*)(wc2s + cn);
                pA += silu_f(acc[n][0])*w.x + silu_f(acc[n][1])*w.y;
                pB += silu_f(acc[n][2])*w.x + silu_f(acc[n][3])*w.y;
            }
            pA += __shfl_xor_sync(0xffffffffu, pA, 1);
            pA += __shfl_xor_sync(0xffffffffu, pA, 2);
            pB += __shfl_xor_sync(0xffffffffu, pB, 1);
            pB += __shfl_xor_sync(0xffffffffu, pB, 2);
            if (t4 == 0) {
                cwpP[g*2 + wip]     = pA;
                cwpP[(g+8)*2 + wip] = pB;
            }
        }
        PBAR(barid);
        // --- stage 4: aggregate diff*cw (3 threads of warp 0 of pair) ---
        if (tid64 < 3) {
            float a = aggxP[tid64];
            #pragma unroll
            for (int e = 0; e < 16; ++e)
                a += diffsP[e*3+tid64]*(cwpP[2*e] + cwpP[2*e+1]);
            aggxP[tid64] = a;
        }
        PBAR(barid);   // protect diffs/cwp/m buffers before next tile
    }

    // epilogue: reduce register aggm over g within warp, write pair partials
    #pragma unroll
    for (int n = 0; n < 8; ++n) {
        #pragma unroll
        for (int j = 0; j < 2; ++j) {
            float v = aggA[n][j];
            v += __shfl_xor_sync(0xffffffffu, v, 4);
            v += __shfl_xor_sync(0xffffffffu, v, 8);
            v += __shfl_xor_sync(0xffffffffu, v, 16);
            if (lane < 4) aggmP[(wip*8+n)*8 + 2*t4 + j] = v;
        }
    }
    __syncthreads();
    if (tid < HD) {
        float a = 0.f;
        #pragma unroll
        for (int p = 0; p < 4; ++p) a += es[W_PAIR + p*PSTR + P_AGGM + tid];
        g_aggm[nidx*HD+tid] = a;
    }
    if (tid < 3) {
        float a = 0.f;
        #pragma unroll
        for (int p = 0; p < 4; ++p) a += es[W_PAIR + p*PSTR + P_AGGX + tid];
        g_aggx[nidx*3+tid] = a;
    }
}

// ------------- node update -------------
__global__ void node_k(int l, const float* __restrict__ Wn1, const float* __restrict__ bn1,
                       const float* __restrict__ Wn2, const float* __restrict__ bn2) {
    __shared__ float ins[WN1R+1];
    __shared__ float hid[HD];
    int nidx = blockIdx.x;
    int tid = threadIdx.x;
    if (tid < FD) ins[tid] = g_feat[nidx*FD+tid];
    ins[FD+tid] = g_aggm[nidx*HD+tid];
    __syncthreads();
    const float* W = Wn1 + l*WN1R*HD;
    float h = bn1[l*HD+tid];
    #pragma unroll 4
    for (int i = 0; i < WN1R; ++i) h = fmaf(ins[i], W[i*HD+tid], h);
    hid[tid] = silu_f(h);
    __syncthreads();
    if (tid < FD) {
        const float* V = Wn2 + l*HD*FD;
        float o = bn2[l*FD+tid];
        #pragma unroll 4
        for (int k = 0; k < HD; ++k) o = fmaf(hid[k], V[k*FD+tid], o);
        g_feat[nidx*FD+tid] += o;
    }
    if (tid < 3) g_x[nidx*3+tid] += g_aggx[nidx*3+tid];
}

// ------------- output -------------
__global__ void final_k(const float* __restrict__ x_h, const float* __restrict__ x_hv,
                        const int* __restrict__ bound, const float* __restrict__ mask,
                        float* __restrict__ out) {
    int idx = blockIdx.x*blockDim.x + threadIdx.x;
    if (idx >= NNODE*3) return;
    int c = idx % 3;
    int n = idx / 3;
    int r = n % NHY;
    int b = n / (NHY*NS);
    int ba = bound[b*NHY+r];
    float x0 = x_h[idx] + x_hv[(b*NV+ba)*3+c];
    out[idx] = (g_x[idx] - x0) * mask[b*NHY+r];
}

extern "C" void kernel_launch(void* const* d_in, const int* in_sizes, int n_in,
                              void* d_out, int out_size) {
    const float* t     = (const float*)d_in[0];
    const float* x_h   = (const float*)d_in[1];
    const float* x_hv  = (const float*)d_in[2];
    const float* bondm = (const float*)d_in[3];
    const float* emhv  = (const float*)d_in[4];
    const float* emhh  = (const float*)d_in[5];
    const float* amask = (const float*)d_in[6];
    const float* W1    = (const float*)d_in[7];
    const float* b1    = (const float*)d_in[8];
    const float* W2    = (const float*)d_in[9];
    const float* b2    = (const float*)d_in[10];
    const float* Wc1   = (const float*)d_in[11];
    const float* bc1   = (const float*)d_in[12];
    const float* Wc2   = (const float*)d_in[13];
    const float* Wn1   = (const float*)d_in[14];
    const float* bn1   = (const float*)d_in[15];
    const float* Wn2   = (const float*)d_in[16];
    const float* bn2   = (const float*)d_in[17];
    const int* pept    = (const int*)d_in[18];
    const int* labv    = (const int*)d_in[19];
    const int* labh    = (const int*)d_in[20];
    const int* posv    = (const int*)d_in[21];
    const int* posh    = (const int*)d_in[22];
    const int* edges   = (const int*)d_in[23];
    const int* bound   = (const int*)d_in[24];
    float* out = (float*)d_out;

    cudaFuncSetAttribute(edge_k, cudaFuncAttributeMaxDynamicSharedMemorySize, EDGE_SMEM_BYTES);

    // launch order keeps the ncu window (-s 5 -c 1) on edge_k:
    // prep(0), wperm(1), nodecb(2), edge(3) <- captured
    prep_k<<<NB + (NNODE+127)/128, 128>>>(edges, emhh, x_h, x_hv, bound, labh, posh, pept);
    wperm_k<<<(4*8192+255)/256, 256>>>(W2, Wc1);
    for (int l = 0; l < NL; ++l) {
        nodecb_k<<<NNODE + (NB*NV*HD+127)/128, HD>>>(l, W1, b1, t, labv, posv, pept);
        edge_k<<<NNODE, ETHREADS, EDGE_SMEM_BYTES>>>(l, W1, b2, bc1, Wc2,
                                                     x_hv, bondm, emhv);
        node_k<<<NNODE, HD>>>(l, Wn1, bn1, Wn2, bn2);
    }
    final_k<<<(NNODE*3+127)/128, 128>>>(x_h, x_hv, bound, amask, out);
}